// round 2
// baseline (speedup 1.0000x reference)
#include <cuda_runtime.h>
#include <math.h>

#define Bsz  4
#define Hn   2
#define Lseq 2048
#define DMod 512
#define DHd  64
#define NHD  128      // Hn*DHd
#define BHn  8        // Bsz*Hn

// scratch (allocation-free rule: __device__ globals)
__device__ float g_q[BHn * Lseq * DHd];
__device__ float g_k[BHn * Lseq * DHd];
__device__ float g_v[BHn * Lseq * DHd];
__device__ float g_ctx[BHn * Lseq * DHd];

// ---------------------------------------------------------------------------
// Projection GEMM: out[bh][i][dh] = X[b*L+i,:] @ W[:, h*64+dh] + bias
// M=8192, K=512, N=128. 64x64 tile, 256 thr, 4x4 micro.
// ---------------------------------------------------------------------------
__global__ void proj_kernel(const float* __restrict__ X, const float* __restrict__ W,
                            const float* __restrict__ bias, float* __restrict__ out)
{
    __shared__ float As[64][17];                 // [m][k], BK=16, padded
    __shared__ __align__(16) float Bs[16][64];   // [k][n]
    const int tid = threadIdx.x;
    const int tx = tid & 15, ty = tid >> 4;
    const int r0 = blockIdx.x * 64;
    const int c0 = blockIdx.y * 64;
    float acc[4][4] = {};
    for (int k0 = 0; k0 < DMod; k0 += 16) {
        #pragma unroll
        for (int l = 0; l < 4; l++) {
            int t = tid + l * 256;
            As[t >> 4][t & 15] = X[(size_t)(r0 + (t >> 4)) * DMod + k0 + (t & 15)];
        }
        #pragma unroll
        for (int l = 0; l < 4; l++) {
            int t = tid + l * 256;
            Bs[t >> 6][t & 63] = W[(size_t)(k0 + (t >> 6)) * NHD + c0 + (t & 63)];
        }
        __syncthreads();
        #pragma unroll
        for (int k = 0; k < 16; k++) {
            float4 bv = *(const float4*)&Bs[k][tx * 4];
            float a[4];
            #pragma unroll
            for (int i = 0; i < 4; i++) a[i] = As[ty * 4 + i][k];
            #pragma unroll
            for (int i = 0; i < 4; i++) {
                acc[i][0] += a[i] * bv.x;
                acc[i][1] += a[i] * bv.y;
                acc[i][2] += a[i] * bv.z;
                acc[i][3] += a[i] * bv.w;
            }
        }
        __syncthreads();
    }
    #pragma unroll
    for (int i = 0; i < 4; i++) {
        int r = r0 + ty * 4 + i;
        int b = r >> 11, ii = r & 2047;
        #pragma unroll
        for (int j = 0; j < 4; j++) {
            int c = c0 + tx * 4 + j;
            int h = c >> 6, dd = c & 63;
            out[(((size_t)((b << 1) + h)) * Lseq + ii) * DHd + dd] = acc[i][j] + bias[c];
        }
    }
}

// ---------------------------------------------------------------------------
// Scores: attn[bh][i][j] = mask ? -10 : 10*tanh( (q_i . k_j) / 8 )
// per (bh): [2048,64] x [2048,64]^T.  64x64 tile, full K=64 in smem.
// Q/K tiles stored transposed [d][i] so both operand reads are LDS.128.
// mask is int32 (bool promoted by harness).
// ---------------------------------------------------------------------------
__global__ void scores_kernel(const float* __restrict__ gq, const float* __restrict__ gk,
                              const int* __restrict__ mask, float* __restrict__ attn)
{
    __shared__ __align__(16) float Qs[64][68];
    __shared__ __align__(16) float Ks[64][68];
    const int bh = blockIdx.z;
    const int b  = bh >> 1;
    const float* q  = gq + (size_t)bh * Lseq * DHd;
    const float* kk = gk + (size_t)bh * Lseq * DHd;
    const int i0 = blockIdx.x * 64;
    const int j0 = blockIdx.y * 64;
    const int tid = threadIdx.x;
    const int tx = tid & 15, ty = tid >> 4;

    #pragma unroll
    for (int l = 0; l < 16; l++) {
        int t = tid + l * 256;
        int d = t & 63, i = t >> 6;
        Qs[d][i] = q[(size_t)(i0 + i) * DHd + d];
        Ks[d][i] = kk[(size_t)(j0 + i) * DHd + d];
    }
    __syncthreads();

    float acc[4][4] = {};
    #pragma unroll
    for (int d = 0; d < 64; d++) {
        float4 av = *(const float4*)&Qs[d][ty * 4];
        float4 bv = *(const float4*)&Ks[d][tx * 4];
        acc[0][0] += av.x * bv.x; acc[0][1] += av.x * bv.y; acc[0][2] += av.x * bv.z; acc[0][3] += av.x * bv.w;
        acc[1][0] += av.y * bv.x; acc[1][1] += av.y * bv.y; acc[1][2] += av.y * bv.z; acc[1][3] += av.y * bv.w;
        acc[2][0] += av.z * bv.x; acc[2][1] += av.z * bv.y; acc[2][2] += av.z * bv.z; acc[2][3] += av.z * bv.w;
        acc[3][0] += av.w * bv.x; acc[3][1] += av.w * bv.y; acc[3][2] += av.w * bv.z; acc[3][3] += av.w * bv.w;
    }

    #pragma unroll
    for (int i = 0; i < 4; i++) {
        int gi = i0 + ty * 4 + i;
        float* row = attn + ((size_t)bh * Lseq + gi) * Lseq;
        #pragma unroll
        for (int j = 0; j < 4; j++) {
            int gj = j0 + tx * 4 + j;
            float val = tanhf(acc[i][j] * 0.125f) * 10.0f;
            if (mask[b * Lseq + gj] != 0) val = -10.0f;
            row[gj] = val;
        }
    }
}

// ---------------------------------------------------------------------------
// In-place row-wise log-softmax over last axis (len 2048). 256 thr, 8 elem/thr.
// ---------------------------------------------------------------------------
__global__ void lsm_kernel(float* __restrict__ attn)
{
    const int row = blockIdx.x;
    float* p = attn + (size_t)row * Lseq;
    const int tid = threadIdx.x;
    __shared__ float red[8];

    float x[8];
    float m = -1e30f;
    #pragma unroll
    for (int l = 0; l < 8; l++) { x[l] = p[tid + l * 256]; m = fmaxf(m, x[l]); }
    #pragma unroll
    for (int o = 16; o; o >>= 1) m = fmaxf(m, __shfl_xor_sync(0xffffffffu, m, o));
    if ((tid & 31) == 0) red[tid >> 5] = m;
    __syncthreads();
    float mall = red[0];
    #pragma unroll
    for (int w = 1; w < 8; w++) mall = fmaxf(mall, red[w]);
    __syncthreads();

    float s = 0.f;
    #pragma unroll
    for (int l = 0; l < 8; l++) s += __expf(x[l] - mall);
    #pragma unroll
    for (int o = 16; o; o >>= 1) s += __shfl_xor_sync(0xffffffffu, s, o);
    if ((tid & 31) == 0) red[tid >> 5] = s;
    __syncthreads();
    float tot = 0.f;
    #pragma unroll
    for (int w = 0; w < 8; w++) tot += red[w];

    float lse = mall + __logf(tot);
    #pragma unroll
    for (int l = 0; l < 8; l++) p[tid + l * 256] = x[l] - lse;
}

// ---------------------------------------------------------------------------
// AV: ctx[bh][i][d] = sum_j attn[bh][i][j] * v[bh][j][d]
// per bh: [2048,2048] x [2048,64]. BM=64, BN=64(full), BK=16.
// ---------------------------------------------------------------------------
__global__ void av_kernel(const float* __restrict__ attn, const float* __restrict__ gv,
                          float* __restrict__ ctx)
{
    __shared__ float As[64][17];
    __shared__ __align__(16) float Bs[16][64];
    const int bh = blockIdx.z;
    const float* a = attn + (size_t)bh * Lseq * Lseq;
    const float* v = gv + (size_t)bh * Lseq * DHd;
    const int i0 = blockIdx.x * 64;
    const int tid = threadIdx.x;
    const int tx = tid & 15, ty = tid >> 4;
    float acc[4][4] = {};
    for (int k0 = 0; k0 < Lseq; k0 += 16) {
        #pragma unroll
        for (int l = 0; l < 4; l++) {
            int t = tid + l * 256;
            As[t >> 4][t & 15] = a[(size_t)(i0 + (t >> 4)) * Lseq + k0 + (t & 15)];
        }
        #pragma unroll
        for (int l = 0; l < 4; l++) {
            int t = tid + l * 256;
            Bs[t >> 6][t & 63] = v[(size_t)(k0 + (t >> 6)) * DHd + (t & 63)];
        }
        __syncthreads();
        #pragma unroll
        for (int k = 0; k < 16; k++) {
            float4 bv = *(const float4*)&Bs[k][tx * 4];
            float a4[4];
            #pragma unroll
            for (int i = 0; i < 4; i++) a4[i] = As[ty * 4 + i][k];
            #pragma unroll
            for (int i = 0; i < 4; i++) {
                acc[i][0] += a4[i] * bv.x;
                acc[i][1] += a4[i] * bv.y;
                acc[i][2] += a4[i] * bv.z;
                acc[i][3] += a4[i] * bv.w;
            }
        }
        __syncthreads();
    }
    #pragma unroll
    for (int i = 0; i < 4; i++) {
        #pragma unroll
        for (int j = 0; j < 4; j++) {
            ctx[((size_t)bh * Lseq + i0 + ty * 4 + i) * DHd + tx * 4 + j] = acc[i][j];
        }
    }
}

// ---------------------------------------------------------------------------
// Output proj: out[b*L+i, n] = ctx[b, :, i, :] (as 128-vec) @ Wo[:, n] + bo[n]
// M=8192, K=128, N=512.
// ---------------------------------------------------------------------------
__global__ void out_kernel(const float* __restrict__ ctx, const float* __restrict__ Wo,
                           const float* __restrict__ bo, float* __restrict__ out)
{
    __shared__ float As[64][17];
    __shared__ __align__(16) float Bs[16][64];
    const int r0 = blockIdx.x * 64;
    const int c0 = blockIdx.y * 64;
    const int tid = threadIdx.x;
    const int tx = tid & 15, ty = tid >> 4;
    float acc[4][4] = {};
    for (int k0 = 0; k0 < NHD; k0 += 16) {
        #pragma unroll
        for (int l = 0; l < 4; l++) {
            int t = tid + l * 256;
            int m = t >> 4, k = t & 15;
            int r = r0 + m, cc = k0 + k;
            int b = r >> 11, ii = r & 2047, h = cc >> 6, dd = cc & 63;
            As[m][k] = ctx[(((size_t)((b << 1) + h)) * Lseq + ii) * DHd + dd];
        }
        #pragma unroll
        for (int l = 0; l < 4; l++) {
            int t = tid + l * 256;
            Bs[t >> 6][t & 63] = Wo[(size_t)(k0 + (t >> 6)) * DMod + c0 + (t & 63)];
        }
        __syncthreads();
        #pragma unroll
        for (int k = 0; k < 16; k++) {
            float4 bv = *(const float4*)&Bs[k][tx * 4];
            float a4[4];
            #pragma unroll
            for (int i = 0; i < 4; i++) a4[i] = As[ty * 4 + i][k];
            #pragma unroll
            for (int i = 0; i < 4; i++) {
                acc[i][0] += a4[i] * bv.x;
                acc[i][1] += a4[i] * bv.y;
                acc[i][2] += a4[i] * bv.z;
                acc[i][3] += a4[i] * bv.w;
            }
        }
        __syncthreads();
    }
    #pragma unroll
    for (int i = 0; i < 4; i++) {
        #pragma unroll
        for (int j = 0; j < 4; j++) {
            int c = c0 + tx * 4 + j;
            out[(size_t)(r0 + ty * 4 + i) * DMod + c] = acc[i][j] + bo[c];
        }
    }
}

// ---------------------------------------------------------------------------
extern "C" void kernel_launch(void* const* d_in, const int* in_sizes, int n_in,
                              void* d_out, int out_size)
{
    const float* Q  = (const float*)d_in[0];
    const float* K  = (const float*)d_in[1];
    const float* V  = (const float*)d_in[2];
    const int*   mask = (const int*)d_in[3];   // bool -> int32 in harness
    const float* Wq = (const float*)d_in[4];
    const float* bq = (const float*)d_in[5];
    const float* Wk = (const float*)d_in[6];
    const float* bk = (const float*)d_in[7];
    const float* Wv = (const float*)d_in[8];
    const float* bv = (const float*)d_in[9];
    const float* Wo = (const float*)d_in[10];
    const float* bo = (const float*)d_in[11];

    float* out  = (float*)d_out;                         // [B, L, 512]
    float* attn = out + (size_t)Bsz * Lseq * DMod;       // [B, H, L, L]

    float *gq, *gk, *gv, *gctx;
    cudaGetSymbolAddress((void**)&gq,   g_q);
    cudaGetSymbolAddress((void**)&gk,   g_k);
    cudaGetSymbolAddress((void**)&gv,   g_v);
    cudaGetSymbolAddress((void**)&gctx, g_ctx);

    dim3 pg(128, 2);
    proj_kernel<<<pg, 256>>>(Q, Wq, bq, gq);
    proj_kernel<<<pg, 256>>>(K, Wk, bk, gk);
    proj_kernel<<<pg, 256>>>(V, Wv, bv, gv);

    scores_kernel<<<dim3(32, 32, BHn), 256>>>(gq, gk, mask, attn);

    lsm_kernel<<<BHn * Lseq, 256>>>(attn);

    av_kernel<<<dim3(32, 1, BHn), 256>>>(attn, gv, gctx);

    out_kernel<<<dim3(128, 8), 256>>>(gctx, Wo, bo, out);
}

// round 3
// speedup vs baseline: 1.2451x; 1.2451x over previous
#include <cuda_runtime.h>
#include <math.h>

#define Lseq 2048
#define BHn  8

// scratch (allocation-free rule: __device__ globals)
__device__ float g_q[BHn * Lseq * 64];
__device__ float g_k[BHn * Lseq * 64];
__device__ float g_v[BHn * Lseq * 64];
__device__ float g_ctx[BHn * Lseq * 64];
__device__ float g_ctx2[4 * BHn * Lseq * 64];   // k-split partials
__device__ float g_sumexp[BHn * Lseq];          // sumexp -> lse (in place)
__device__ float g_colsum[BHn * 64];            // per-(bh) column sums of v

// ---------------------------------------------------------------------------
// zero sumexp + colsum
// ---------------------------------------------------------------------------
__global__ void zero_kernel(float* __restrict__ sumexp, float* __restrict__ colsum)
{
    if (blockIdx.x < 16) {
        int g = blockIdx.x * 256 + threadIdx.x;      // 4096 float4 = 16384 floats
        ((float4*)sumexp)[g] = make_float4(0.f, 0.f, 0.f, 0.f);
    } else {
        if (threadIdx.x < 128)                        // 512 floats
            ((float4*)colsum)[threadIdx.x] = make_float4(0.f, 0.f, 0.f, 0.f);
    }
}

// ---------------------------------------------------------------------------
// Fused QKV projection: dst[bh][i][dh] = X @ W + bias. M=8192, K=512, N=128.
// 128x128 tile, 256 thr, 8x8 micro, which = blockIdx.y selects Q/K/V.
// ---------------------------------------------------------------------------
__global__ __launch_bounds__(256) void proj3_kernel(
    const float* __restrict__ Q, const float* __restrict__ K, const float* __restrict__ V,
    const float* __restrict__ Wq, const float* __restrict__ bq,
    const float* __restrict__ Wk, const float* __restrict__ bk,
    const float* __restrict__ Wv, const float* __restrict__ bv,
    float* __restrict__ gq, float* __restrict__ gk, float* __restrict__ gv)
{
    __shared__ float Xs[16][132];
    __shared__ __align__(16) float Ws[16][128];
    const int which = blockIdx.y;
    const float* X    = which == 0 ? Q  : (which == 1 ? K  : V);
    const float* W    = which == 0 ? Wq : (which == 1 ? Wk : Wv);
    const float* bias = which == 0 ? bq : (which == 1 ? bk : bv);
    float*       dst  = which == 0 ? gq : (which == 1 ? gk : gv);
    const int r0 = blockIdx.x * 128;
    const int tid = threadIdx.x;
    const int tx = tid & 15, ty = tid >> 4;
    float acc[8][8] = {};
    for (int k0 = 0; k0 < 512; k0 += 16) {
        #pragma unroll
        for (int l = 0; l < 2; l++) {
            int u = tid + l * 256;
            int k4 = u & 3, m = u >> 2;
            float4 xv = *(const float4*)&X[(size_t)(r0 + m) * 512 + k0 + k4 * 4];
            Xs[k4*4+0][m] = xv.x; Xs[k4*4+1][m] = xv.y;
            Xs[k4*4+2][m] = xv.z; Xs[k4*4+3][m] = xv.w;
        }
        #pragma unroll
        for (int l = 0; l < 2; l++) {
            int u = tid + l * 256;
            int n4 = u & 31, k = u >> 5;
            *(float4*)&Ws[k][n4*4] = *(const float4*)&W[(size_t)(k0 + k) * 128 + n4*4];
        }
        __syncthreads();
        #pragma unroll
        for (int k = 0; k < 16; k++) {
            float4 a0 = *(const float4*)&Xs[k][ty*8];
            float4 a1 = *(const float4*)&Xs[k][ty*8+4];
            float4 b0 = *(const float4*)&Ws[k][tx*4];
            float4 b1 = *(const float4*)&Ws[k][64 + tx*4];
            float ar[8] = {a0.x,a0.y,a0.z,a0.w,a1.x,a1.y,a1.z,a1.w};
            float br[8] = {b0.x,b0.y,b0.z,b0.w,b1.x,b1.y,b1.z,b1.w};
            #pragma unroll
            for (int i = 0; i < 8; i++)
                #pragma unroll
                for (int j = 0; j < 8; j++) acc[i][j] += ar[i] * br[j];
        }
        __syncthreads();
    }
    #pragma unroll
    for (int i = 0; i < 8; i++) {
        int r = r0 + ty*8 + i;
        int b = r >> 11, ii = r & 2047;
        #pragma unroll
        for (int half = 0; half < 2; half++) {
            int c = half*64 + tx*4;
            int h = c >> 6, dd = c & 63;
            float4 o;
            o.x = acc[i][half*4+0] + bias[c+0];
            o.y = acc[i][half*4+1] + bias[c+1];
            o.z = acc[i][half*4+2] + bias[c+2];
            o.w = acc[i][half*4+3] + bias[c+3];
            *(float4*)&dst[(((size_t)(b*2 + h)) * 2048 + ii) * 64 + dd] = o;
        }
    }
}

// ---------------------------------------------------------------------------
// colsum[bh][d] = sum_j v[bh][j][d]   (grid: 8 x 8, 256 thr, atomics)
// ---------------------------------------------------------------------------
__global__ void colsum_kernel(const float* __restrict__ gv, float* __restrict__ colsum)
{
    __shared__ float red[256];
    const int bh = blockIdx.x;
    const int tid = threadIdx.x;
    const int c = tid & 63, p = tid >> 6;
    const float* v = gv + (size_t)bh * 2048 * 64;
    int jb = blockIdx.y * 256 + p * 64;
    float s = 0.f;
    #pragma unroll 8
    for (int j = 0; j < 64; j++) s += v[(size_t)(jb + j) * 64 + c];
    red[tid] = s;
    __syncthreads();
    if (tid < 64)
        atomicAdd(&colsum[bh * 64 + c], red[tid] + red[tid+64] + red[tid+128] + red[tid+192]);
}

// ---------------------------------------------------------------------------
// Scores: x = mask ? -10 : 10*tanh(qk/8); write raw x to attn; atomic row sumexp.
// 128x128 tile, 8x8 micro, swizzled transposed Q/K tiles, d chunked 32.
// ---------------------------------------------------------------------------
__global__ __launch_bounds__(256) void scores_kernel(
    const float* __restrict__ gq, const float* __restrict__ gk,
    const int* __restrict__ mask, float* __restrict__ attn, float* __restrict__ sumexp)
{
    __shared__ float Qs[32][128];
    __shared__ float Ks[32][128];
    const int bh = blockIdx.z, b = bh >> 1;
    const float* q  = gq + (size_t)bh * 2048 * 64;
    const float* kk = gk + (size_t)bh * 2048 * 64;
    const int i0 = blockIdx.x * 128, j0 = blockIdx.y * 128;
    const int tid = threadIdx.x;
    const int tx = tid & 15, ty = tid >> 4;
    float acc[8][8] = {};

    #pragma unroll
    for (int dc = 0; dc < 64; dc += 32) {
        #pragma unroll
        for (int l = 0; l < 4; l++) {
            int u = tid + l * 256;
            int d4 = u & 7, i = u >> 3;
            float4 qv = *(const float4*)&q [(size_t)(i0 + i) * 64 + dc + d4*4];
            float4 kv = *(const float4*)&kk[(size_t)(j0 + i) * 64 + dc + d4*4];
            int isw = i ^ (d4 << 2);
            Qs[d4*4+0][isw] = qv.x; Qs[d4*4+1][isw] = qv.y;
            Qs[d4*4+2][isw] = qv.z; Qs[d4*4+3][isw] = qv.w;
            Ks[d4*4+0][isw] = kv.x; Ks[d4*4+1][isw] = kv.y;
            Ks[d4*4+2][isw] = kv.z; Ks[d4*4+3][isw] = kv.w;
        }
        __syncthreads();
        #pragma unroll
        for (int d = 0; d < 32; d++) {
            int sw = (d >> 2) << 2;
            float4 a0 = *(const float4*)&Qs[d][(ty*8)    ^ sw];
            float4 a1 = *(const float4*)&Qs[d][(ty*8+4)  ^ sw];
            float4 b0 = *(const float4*)&Ks[d][(tx*4)    ^ sw];
            float4 b1 = *(const float4*)&Ks[d][(64+tx*4) ^ sw];
            float ar[8] = {a0.x,a0.y,a0.z,a0.w,a1.x,a1.y,a1.z,a1.w};
            float br[8] = {b0.x,b0.y,b0.z,b0.w,b1.x,b1.y,b1.z,b1.w};
            #pragma unroll
            for (int i = 0; i < 8; i++)
                #pragma unroll
                for (int j = 0; j < 8; j++) acc[i][j] += ar[i] * br[j];
        }
        __syncthreads();
    }

    // mask for my 8 columns
    int4 m0 = *(const int4*)&mask[b * 2048 + j0 + tx*4];
    int4 m1 = *(const int4*)&mask[b * 2048 + j0 + 64 + tx*4];
    int mk[8] = {m0.x, m0.y, m0.z, m0.w, m1.x, m1.y, m1.z, m1.w};

    float rowsum[8];
    #pragma unroll
    for (int i = 0; i < 8; i++) {
        int gi = i0 + ty*8 + i;
        float* row = attn + ((size_t)bh * 2048 + gi) * 2048;
        float vals[8];
        float rs = 0.f;
        #pragma unroll
        for (int j = 0; j < 8; j++) {
            float e2s = __expf(acc[i][j] * 0.25f);          // exp(2 * (qk/8))
            float val = 10.0f - 20.0f / (e2s + 1.0f);       // 10*tanh(qk/8)
            if (mk[j] != 0) val = -10.0f;
            vals[j] = val;
            rs += __expf(val);
        }
        rowsum[i] = rs;
        *(float4*)&row[j0 + tx*4]      = make_float4(vals[0], vals[1], vals[2], vals[3]);
        *(float4*)&row[j0 + 64 + tx*4] = make_float4(vals[4], vals[5], vals[6], vals[7]);
    }
    #pragma unroll
    for (int i = 0; i < 8; i++) {
        float rs = rowsum[i];
        rs += __shfl_xor_sync(0xffffffffu, rs, 1);
        rs += __shfl_xor_sync(0xffffffffu, rs, 2);
        rs += __shfl_xor_sync(0xffffffffu, rs, 4);
        rs += __shfl_xor_sync(0xffffffffu, rs, 8);
        if (tx == 0) atomicAdd(&sumexp[bh * 2048 + i0 + ty*8 + i], rs);
    }
}

// ---------------------------------------------------------------------------
// lse = log(sumexp), in place (16384 floats)
// ---------------------------------------------------------------------------
__global__ void lse_kernel(float* __restrict__ sumexp)
{
    int g = blockIdx.x * 256 + threadIdx.x;
    float4 v = ((float4*)sumexp)[g];
    v.x = __logf(v.x); v.y = __logf(v.y); v.z = __logf(v.z); v.w = __logf(v.w);
    ((float4*)sumexp)[g] = v;
}

// ---------------------------------------------------------------------------
// AV partial: ctx2[ks][bh][i][d] = sum_{k in split} x[i][k]*v[k][d]
// + fused attn normalize write-back (x -> x - lse[i]).
// 128x64 tile, 128 thr, 8x8 micro, 4-way k split.
// ---------------------------------------------------------------------------
__global__ __launch_bounds__(128) void av_kernel(
    float* __restrict__ attn, const float* __restrict__ gv,
    const float* __restrict__ lse, float* __restrict__ ctx2)
{
    __shared__ float As[16][132];
    __shared__ __align__(16) float Bs[16][64];
    __shared__ float ls[128];
    const int bh = blockIdx.z;
    const int i0 = blockIdx.x * 128;
    const int ks = blockIdx.y;
    const int tid = threadIdx.x;
    const int tx = tid & 7, ty = tid >> 3;
    float* a = attn + (size_t)bh * 2048 * 2048;
    const float* v = gv + (size_t)bh * 2048 * 64;
    ls[tid] = lse[bh * 2048 + i0 + tid];
    __syncthreads();
    float acc[8][8] = {};
    for (int k0 = ks * 512; k0 < ks * 512 + 512; k0 += 16) {
        #pragma unroll
        for (int l = 0; l < 4; l++) {
            int u = tid + l * 128;
            int k4 = u & 3, m = u >> 2;
            size_t gi = ((size_t)(i0 + m)) * 2048 + k0 + k4*4;
            float4 x = *(const float4*)&a[gi];
            float lv = ls[m];
            *(float4*)&a[gi] = make_float4(x.x - lv, x.y - lv, x.z - lv, x.w - lv);
            As[k4*4+0][m] = x.x; As[k4*4+1][m] = x.y;
            As[k4*4+2][m] = x.z; As[k4*4+3][m] = x.w;
        }
        #pragma unroll
        for (int l = 0; l < 2; l++) {
            int u = tid + l * 128;
            int d4 = u & 15, k = u >> 4;
            *(float4*)&Bs[k][d4*4] = *(const float4*)&v[(size_t)(k0 + k) * 64 + d4*4];
        }
        __syncthreads();
        #pragma unroll
        for (int k = 0; k < 16; k++) {
            float4 a0 = *(const float4*)&As[k][ty*8];
            float4 a1 = *(const float4*)&As[k][ty*8+4];
            float4 b0 = *(const float4*)&Bs[k][tx*4];
            float4 b1 = *(const float4*)&Bs[k][32 + tx*4];
            float ar[8] = {a0.x,a0.y,a0.z,a0.w,a1.x,a1.y,a1.z,a1.w};
            float br[8] = {b0.x,b0.y,b0.z,b0.w,b1.x,b1.y,b1.z,b1.w};
            #pragma unroll
            for (int i = 0; i < 8; i++)
                #pragma unroll
                for (int j = 0; j < 8; j++) acc[i][j] += ar[i] * br[j];
        }
        __syncthreads();
    }
    float* dst = ctx2 + ((size_t)ks * 8 + bh) * 2048 * 64;
    #pragma unroll
    for (int i = 0; i < 8; i++) {
        size_t r = (size_t)(i0 + ty*8 + i) * 64;
        *(float4*)&dst[r + tx*4]      = make_float4(acc[i][0], acc[i][1], acc[i][2], acc[i][3]);
        *(float4*)&dst[r + 32 + tx*4] = make_float4(acc[i][4], acc[i][5], acc[i][6], acc[i][7]);
    }
}

// ---------------------------------------------------------------------------
// ctx = sum_s ctx2[s] - lse[i]*colsum[d]
// ---------------------------------------------------------------------------
__global__ void reduce_ctx_kernel(const float* __restrict__ ctx2,
    const float* __restrict__ lse, const float* __restrict__ colsum,
    float* __restrict__ ctx)
{
    int g = blockIdx.x * 256 + threadIdx.x;    // f4 index < 262144
    int elem = g * 4;
    int bh = elem >> 17;
    int i  = (elem >> 6) & 2047;
    int d  = elem & 63;
    const float4* c2 = (const float4*)ctx2;
    float4 s  = c2[g];
    float4 t1 = c2[262144 + g];
    float4 t2 = c2[524288 + g];
    float4 t3 = c2[786432 + g];
    s.x += t1.x + t2.x + t3.x; s.y += t1.y + t2.y + t3.y;
    s.z += t1.z + t2.z + t3.z; s.w += t1.w + t2.w + t3.w;
    float l = lse[bh * 2048 + i];
    float4 cs = *(const float4*)&colsum[bh * 64 + d];
    s.x -= l * cs.x; s.y -= l * cs.y; s.z -= l * cs.z; s.w -= l * cs.w;
    ((float4*)ctx)[g] = s;
}

// ---------------------------------------------------------------------------
// Output proj: M=8192, K=128, N=512. 128x128 tile, 8x8 micro.
// ---------------------------------------------------------------------------
__global__ __launch_bounds__(256) void out_kernel(
    const float* __restrict__ ctx, const float* __restrict__ Wo,
    const float* __restrict__ bo, float* __restrict__ out)
{
    __shared__ float As[16][132];
    __shared__ __align__(16) float Ws[16][128];
    const int r0 = blockIdx.x * 128, c0 = blockIdx.y * 128;
    const int tid = threadIdx.x;
    const int tx = tid & 15, ty = tid >> 4;
    float acc[8][8] = {};
    for (int k0 = 0; k0 < 128; k0 += 16) {
        #pragma unroll
        for (int l = 0; l < 2; l++) {
            int u = tid + l * 256;
            int k4 = u & 3, m = u >> 2;
            int r = r0 + m;
            int b = r >> 11, ii = r & 2047;
            int k = k0 + k4*4;
            int h = k >> 6, dd = k & 63;
            float4 xv = *(const float4*)&ctx[(((size_t)(b*2 + h)) * 2048 + ii) * 64 + dd];
            As[k4*4+0][m] = xv.x; As[k4*4+1][m] = xv.y;
            As[k4*4+2][m] = xv.z; As[k4*4+3][m] = xv.w;
        }
        #pragma unroll
        for (int l = 0; l < 2; l++) {
            int u = tid + l * 256;
            int n4 = u & 31, k = u >> 5;
            *(float4*)&Ws[k][n4*4] = *(const float4*)&Wo[(size_t)(k0 + k) * 512 + c0 + n4*4];
        }
        __syncthreads();
        #pragma unroll
        for (int k = 0; k < 16; k++) {
            float4 a0 = *(const float4*)&As[k][ty*8];
            float4 a1 = *(const float4*)&As[k][ty*8+4];
            float4 b0 = *(const float4*)&Ws[k][tx*4];
            float4 b1 = *(const float4*)&Ws[k][64 + tx*4];
            float ar[8] = {a0.x,a0.y,a0.z,a0.w,a1.x,a1.y,a1.z,a1.w};
            float br[8] = {b0.x,b0.y,b0.z,b0.w,b1.x,b1.y,b1.z,b1.w};
            #pragma unroll
            for (int i = 0; i < 8; i++)
                #pragma unroll
                for (int j = 0; j < 8; j++) acc[i][j] += ar[i] * br[j];
        }
        __syncthreads();
    }
    #pragma unroll
    for (int i = 0; i < 8; i++) {
        size_t r = (size_t)(r0 + ty*8 + i) * 512;
        #pragma unroll
        for (int half = 0; half < 2; half++) {
            int c = c0 + half*64 + tx*4;
            float4 o;
            o.x = acc[i][half*4+0] + bo[c+0];
            o.y = acc[i][half*4+1] + bo[c+1];
            o.z = acc[i][half*4+2] + bo[c+2];
            o.w = acc[i][half*4+3] + bo[c+3];
            *(float4*)&out[r + c] = o;
        }
    }
}

// ---------------------------------------------------------------------------
extern "C" void kernel_launch(void* const* d_in, const int* in_sizes, int n_in,
                              void* d_out, int out_size)
{
    const float* Q  = (const float*)d_in[0];
    const float* K  = (const float*)d_in[1];
    const float* V  = (const float*)d_in[2];
    const int*   mask = (const int*)d_in[3];   // bool -> int32 in harness
    const float* Wq = (const float*)d_in[4];
    const float* bq = (const float*)d_in[5];
    const float* Wk = (const float*)d_in[6];
    const float* bk = (const float*)d_in[7];
    const float* Wv = (const float*)d_in[8];
    const float* bv = (const float*)d_in[9];
    const float* Wo = (const float*)d_in[10];
    const float* bo = (const float*)d_in[11];

    float* out  = (float*)d_out;                      // [B, L, 512]
    float* attn = out + (size_t)4 * 2048 * 512;       // [B, H, L, L]

    float *gq, *gk, *gv, *gctx, *gctx2, *gse, *gcs;
    cudaGetSymbolAddress((void**)&gq,    g_q);
    cudaGetSymbolAddress((void**)&gk,    g_k);
    cudaGetSymbolAddress((void**)&gv,    g_v);
    cudaGetSymbolAddress((void**)&gctx,  g_ctx);
    cudaGetSymbolAddress((void**)&gctx2, g_ctx2);
    cudaGetSymbolAddress((void**)&gse,   g_sumexp);
    cudaGetSymbolAddress((void**)&gcs,   g_colsum);

    zero_kernel<<<17, 256>>>(gse, gcs);
    proj3_kernel<<<dim3(64, 3), 256>>>(Q, K, V, Wq, bq, Wk, bk, Wv, bv, gq, gk, gv);
    colsum_kernel<<<dim3(8, 8), 256>>>(gv, gcs);
    scores_kernel<<<dim3(16, 16, 8), 256>>>(gq, gk, mask, attn, gse);
    lse_kernel<<<16, 256>>>(gse);
    av_kernel<<<dim3(16, 4, 8), 128>>>(attn, gv, gse, gctx2);
    reduce_ctx_kernel<<<1024, 256>>>(gctx2, gse, gcs, gctx);
    out_kernel<<<dim3(64, 4), 256>>>(gctx, Wo, bo, out);
}

// round 5
// speedup vs baseline: 1.4003x; 1.1246x over previous
#include <cuda_runtime.h>
#include <cuda_bf16.h>
#include <math.h>
#include <stdint.h>

#define Lseq 2048
#define BHn  8

// scratch (allocation-free rule: __device__ globals)
__device__ float g_v[BHn * Lseq * 64];
__device__ float g_ctx[BHn * Lseq * 64];
__device__ float g_ctx2[4 * BHn * Lseq * 64];   // k-split partials
__device__ float g_sumexp[BHn * Lseq];          // sumexp -> lse (in place)
__device__ float g_colsum[BHn * 64];            // per-(bh) column sums of v
__device__ __nv_bfloat16 g_qh[BHn * Lseq * 64];
__device__ __nv_bfloat16 g_ql[BHn * Lseq * 64];
__device__ __nv_bfloat16 g_kh[BHn * Lseq * 64];
__device__ __nv_bfloat16 g_kl[BHn * Lseq * 64];

__device__ __forceinline__ uint32_t smem_u32(const void* p) {
    uint32_t a;
    asm("{ .reg .u64 t; cvta.to.shared.u64 t, %1; cvt.u32.u64 %0, t; }" : "=r"(a) : "l"(p));
    return a;
}
__device__ __forceinline__ void ldsm_x4(uint32_t* r, uint32_t addr) {
    asm volatile("ldmatrix.sync.aligned.m8n8.x4.shared.b16 {%0,%1,%2,%3}, [%4];"
        : "=r"(r[0]), "=r"(r[1]), "=r"(r[2]), "=r"(r[3]) : "r"(addr));
}
__device__ __forceinline__ void mma_bf16(float* c, const uint32_t* a, const uint32_t* b) {
    asm volatile("mma.sync.aligned.m16n8k16.row.col.f32.bf16.bf16.f32 "
        "{%0,%1,%2,%3}, {%4,%5,%6,%7}, {%8,%9}, {%0,%1,%2,%3};"
        : "+f"(c[0]), "+f"(c[1]), "+f"(c[2]), "+f"(c[3])
        : "r"(a[0]), "r"(a[1]), "r"(a[2]), "r"(a[3]), "r"(b[0]), "r"(b[1]));
}

// ---------------------------------------------------------------------------
__global__ void zero_kernel(float* __restrict__ sumexp, float* __restrict__ colsum)
{
    if (blockIdx.x < 16) {
        int g = blockIdx.x * 256 + threadIdx.x;
        ((float4*)sumexp)[g] = make_float4(0.f, 0.f, 0.f, 0.f);
    } else if (threadIdx.x < 128) {
        ((float4*)colsum)[threadIdx.x] = make_float4(0.f, 0.f, 0.f, 0.f);
    }
}

// ---------------------------------------------------------------------------
// Fused QKV projection. which==0/1: write bf16 hi/lo (q/k). which==2: fp32 v.
// ---------------------------------------------------------------------------
__global__ __launch_bounds__(256) void proj3_kernel(
    const float* __restrict__ Q, const float* __restrict__ K, const float* __restrict__ V,
    const float* __restrict__ Wq, const float* __restrict__ bq,
    const float* __restrict__ Wk, const float* __restrict__ bk,
    const float* __restrict__ Wv, const float* __restrict__ bv,
    __nv_bfloat16* __restrict__ qh, __nv_bfloat16* __restrict__ ql,
    __nv_bfloat16* __restrict__ kh, __nv_bfloat16* __restrict__ kl,
    float* __restrict__ gv)
{
    __shared__ float Xs[16][132];
    __shared__ __align__(16) float Ws[16][128];
    const int which = blockIdx.y;
    const float* X    = which == 0 ? Q  : (which == 1 ? K  : V);
    const float* W    = which == 0 ? Wq : (which == 1 ? Wk : Wv);
    const float* bias = which == 0 ? bq : (which == 1 ? bk : bv);
    const int r0 = blockIdx.x * 128;
    const int tid = threadIdx.x;
    const int tx = tid & 15, ty = tid >> 4;
    float acc[8][8] = {};
    for (int k0 = 0; k0 < 512; k0 += 16) {
        #pragma unroll
        for (int l = 0; l < 2; l++) {
            int u = tid + l * 256;
            int k4 = u & 3, m = u >> 2;
            float4 xv = *(const float4*)&X[(size_t)(r0 + m) * 512 + k0 + k4 * 4];
            Xs[k4*4+0][m] = xv.x; Xs[k4*4+1][m] = xv.y;
            Xs[k4*4+2][m] = xv.z; Xs[k4*4+3][m] = xv.w;
        }
        #pragma unroll
        for (int l = 0; l < 2; l++) {
            int u = tid + l * 256;
            int n4 = u & 31, k = u >> 5;
            *(float4*)&Ws[k][n4*4] = *(const float4*)&W[(size_t)(k0 + k) * 128 + n4*4];
        }
        __syncthreads();
        #pragma unroll
        for (int k = 0; k < 16; k++) {
            float4 a0 = *(const float4*)&Xs[k][ty*8];
            float4 a1 = *(const float4*)&Xs[k][ty*8+4];
            float4 b0 = *(const float4*)&Ws[k][tx*4];
            float4 b1 = *(const float4*)&Ws[k][64 + tx*4];
            float ar[8] = {a0.x,a0.y,a0.z,a0.w,a1.x,a1.y,a1.z,a1.w};
            float br[8] = {b0.x,b0.y,b0.z,b0.w,b1.x,b1.y,b1.z,b1.w};
            #pragma unroll
            for (int i = 0; i < 8; i++)
                #pragma unroll
                for (int j = 0; j < 8; j++) acc[i][j] += ar[i] * br[j];
        }
        __syncthreads();
    }
    #pragma unroll
    for (int i = 0; i < 8; i++) {
        int r = r0 + ty*8 + i;
        int b = r >> 11, ii = r & 2047;
        #pragma unroll
        for (int half = 0; half < 2; half++) {
            int c = half*64 + tx*4;
            int h = c >> 6, dd = c & 63;
            float4 o;
            o.x = acc[i][half*4+0] + bias[c+0];
            o.y = acc[i][half*4+1] + bias[c+1];
            o.z = acc[i][half*4+2] + bias[c+2];
            o.w = acc[i][half*4+3] + bias[c+3];
            size_t idx = (((size_t)(b*2 + h)) * 2048 + ii) * 64 + dd;
            if (which == 2) {
                *(float4*)&gv[idx] = o;
            } else {
                __nv_bfloat16 hx = __float2bfloat16(o.x), hy = __float2bfloat16(o.y);
                __nv_bfloat16 hz = __float2bfloat16(o.z), hw = __float2bfloat16(o.w);
                __nv_bfloat16 lx = __float2bfloat16(o.x - __bfloat162float(hx));
                __nv_bfloat16 ly = __float2bfloat16(o.y - __bfloat162float(hy));
                __nv_bfloat16 lz = __float2bfloat16(o.z - __bfloat162float(hz));
                __nv_bfloat16 lw = __float2bfloat16(o.w - __bfloat162float(hw));
                __nv_bfloat16* ph = (which == 0 ? qh : kh) + idx;
                __nv_bfloat16* pl = (which == 0 ? ql : kl) + idx;
                __nv_bfloat162 h01; h01.x = hx; h01.y = hy;
                __nv_bfloat162 h23; h23.x = hz; h23.y = hw;
                __nv_bfloat162 l01; l01.x = lx; l01.y = ly;
                __nv_bfloat162 l23; l23.x = lz; l23.y = lw;
                ((__nv_bfloat162*)ph)[0] = h01; ((__nv_bfloat162*)ph)[1] = h23;
                ((__nv_bfloat162*)pl)[0] = l01; ((__nv_bfloat162*)pl)[1] = l23;
            }
        }
    }
}

// ---------------------------------------------------------------------------
__global__ void colsum_kernel(const float* __restrict__ gv, float* __restrict__ colsum)
{
    __shared__ float red[256];
    const int bh = blockIdx.x;
    const int tid = threadIdx.x;
    const int c = tid & 63, p = tid >> 6;
    const float* v = gv + (size_t)bh * 2048 * 64;
    int jb = blockIdx.y * 256 + p * 64;
    float s = 0.f;
    #pragma unroll 8
    for (int j = 0; j < 64; j++) s += v[(size_t)(jb + j) * 64 + c];
    red[tid] = s;
    __syncthreads();
    if (tid < 64)
        atomicAdd(&colsum[bh * 64 + c], red[tid] + red[tid+64] + red[tid+128] + red[tid+192]);
}

// ---------------------------------------------------------------------------
// mma.sync scores: D = Q K^T via bf16 split (hh + hl + lh), fp32 accum.
// CTA 128x128, 8 warps (4m x 2n), warp tile 32x64 (2 x 8 m16n8k16 frags).
// smem: 4 tiles [128 rows x 144B] (qh,ql,kh,kl) = 73728B, then 128 ints mask.
// epilogue reuses tile region as 128x132 f32 staging for coalesced stores.
// ---------------------------------------------------------------------------
__global__ __launch_bounds__(256, 2) void scores_mma_kernel(
    const __nv_bfloat16* __restrict__ gqh, const __nv_bfloat16* __restrict__ gql,
    const __nv_bfloat16* __restrict__ gkh, const __nv_bfloat16* __restrict__ gkl,
    const int* __restrict__ mask, float* __restrict__ attn, float* __restrict__ sumexp)
{
    extern __shared__ char smem[];
    const int tid = threadIdx.x, wid = tid >> 5, lid = tid & 31;
    const int bh = blockIdx.z, b = bh >> 1;
    const int i0 = blockIdx.x * 128, j0 = blockIdx.y * 128;
    const int wm = wid & 3, wn = wid >> 2;

    char* tQH = smem;
    char* tQL = smem + 18432;
    char* tKH = smem + 36864;
    char* tKL = smem + 55296;
    int*  smk = (int*)(smem + 73728);

    // load 4 tiles: 128 rows x 64 bf16 (128B) -> smem rows of 144B (pad 16B)
    {
        const float4* s0 = (const float4*)(gqh + ((size_t)bh * 2048 + i0) * 64);
        const float4* s1 = (const float4*)(gql + ((size_t)bh * 2048 + i0) * 64);
        const float4* s2 = (const float4*)(gkh + ((size_t)bh * 2048 + j0) * 64);
        const float4* s3 = (const float4*)(gkl + ((size_t)bh * 2048 + j0) * 64);
        #pragma unroll
        for (int l = 0; l < 4; l++) {
            int u = tid + l * 256;
            int row = u >> 3, ch = u & 7;
            int off = row * 144 + ch * 16;
            *(float4*)(tQH + off) = s0[u];
            *(float4*)(tQL + off) = s1[u];
            *(float4*)(tKH + off) = s2[u];
            *(float4*)(tKL + off) = s3[u];
        }
    }
    if (tid < 128) smk[tid] = mask[b * 2048 + j0 + tid];
    __syncthreads();

    // fragment addresses (byte offsets within a tile)
    const uint32_t aOff = (uint32_t)((wm * 32 + (lid & 15)) * 144 + ((lid >> 4) << 4));
    const uint32_t bOff = (uint32_t)((wn * 64 + ((lid & 16) >> 1) + (lid & 7)) * 144
                                     + ((lid & 8) << 1));

    float acc[2][8][4] = {};
    const uint32_t qb[3] = { smem_u32(tQH), smem_u32(tQH), smem_u32(tQL) };
    const uint32_t kb[3] = { smem_u32(tKH), smem_u32(tKL), smem_u32(tKH) };

    #pragma unroll
    for (int t = 0; t < 3; t++) {
        const uint32_t qa = qb[t] + aOff;
        const uint32_t ka = kb[t] + bOff;
        #pragma unroll
        for (int ks = 0; ks < 4; ks++) {
            uint32_t af[2][4], bf[4][4];
            ldsm_x4(af[0], qa + ks * 32);
            ldsm_x4(af[1], qa + ks * 32 + 16 * 144);
            #pragma unroll
            for (int np = 0; np < 4; np++)
                ldsm_x4(bf[np], ka + ks * 32 + np * 16 * 144);
            #pragma unroll
            for (int mi = 0; mi < 2; mi++)
                #pragma unroll
                for (int np = 0; np < 4; np++) {
                    mma_bf16(acc[mi][np*2],   af[mi], &bf[np][0]);
                    mma_bf16(acc[mi][np*2+1], af[mi], &bf[np][2]);
                }
        }
    }
    __syncthreads();   // tiles consumed; smem becomes staging buffer

    // epilogue
    float* buf = (float*)smem;             // [128][132]
    const int g = lid >> 2, qid = lid & 3;
    float rs[2][2] = {};
    #pragma unroll
    for (int mi = 0; mi < 2; mi++) {
        const int row0 = wm * 32 + mi * 16 + g;
        #pragma unroll
        for (int ni = 0; ni < 8; ni++) {
            const int col = wn * 64 + ni * 8 + qid * 2;
            const int m0 = smk[col], m1 = smk[col + 1];
            float v0 = acc[mi][ni][0], v1 = acc[mi][ni][1];
            float v2 = acc[mi][ni][2], v3 = acc[mi][ni][3];
            v0 = 10.0f - 20.0f / (__expf(v0 * 0.25f) + 1.0f);
            v1 = 10.0f - 20.0f / (__expf(v1 * 0.25f) + 1.0f);
            v2 = 10.0f - 20.0f / (__expf(v2 * 0.25f) + 1.0f);
            v3 = 10.0f - 20.0f / (__expf(v3 * 0.25f) + 1.0f);
            if (m0) { v0 = -10.0f; v2 = -10.0f; }
            if (m1) { v1 = -10.0f; v3 = -10.0f; }
            rs[mi][0] += __expf(v0) + __expf(v1);
            rs[mi][1] += __expf(v2) + __expf(v3);
            *(float2*)&buf[row0 * 132 + col]       = make_float2(v0, v1);
            *(float2*)&buf[(row0 + 8) * 132 + col] = make_float2(v2, v3);
        }
    }
    #pragma unroll
    for (int mi = 0; mi < 2; mi++)
        #pragma unroll
        for (int hl = 0; hl < 2; hl++) {
            float r = rs[mi][hl];
            r += __shfl_xor_sync(0xffffffffu, r, 1);
            r += __shfl_xor_sync(0xffffffffu, r, 2);
            if (qid == 0)
                atomicAdd(&sumexp[bh * 2048 + i0 + wm * 32 + mi * 16 + hl * 8 + g], r);
        }
    __syncthreads();

    // coalesced store of the 128x128 tile
    #pragma unroll
    for (int l = 0; l < 16; l++) {
        int idx = tid + l * 256;
        int row = idx >> 5, c4 = idx & 31;
        float4 v = *(const float4*)&buf[row * 132 + c4 * 4];
        *(float4*)(attn + ((size_t)bh * 2048 + i0 + row) * 2048 + j0 + c4 * 4) = v;
    }
}

// ---------------------------------------------------------------------------
__global__ void lse_kernel(float* __restrict__ sumexp)
{
    int g = blockIdx.x * 256 + threadIdx.x;
    float4 v = ((float4*)sumexp)[g];
    v.x = __logf(v.x); v.y = __logf(v.y); v.z = __logf(v.z); v.w = __logf(v.w);
    ((float4*)sumexp)[g] = v;
}

// ---------------------------------------------------------------------------
// AV partial + fused attn normalize write-back (x -> x - lse[i]).
// ---------------------------------------------------------------------------
__global__ __launch_bounds__(128) void av_kernel(
    float* __restrict__ attn, const float* __restrict__ gv,
    const float* __restrict__ lse, float* __restrict__ ctx2)
{
    __shared__ float As[16][132];
    __shared__ __align__(16) float Bs[16][64];
    __shared__ float ls[128];
    const int bh = blockIdx.z;
    const int i0 = blockIdx.x * 128;
    const int ks = blockIdx.y;
    const int tid = threadIdx.x;
    const int tx = tid & 7, ty = tid >> 3;
    float* a = attn + (size_t)bh * 2048 * 2048;
    const float* v = gv + (size_t)bh * 2048 * 64;
    ls[tid] = lse[bh * 2048 + i0 + tid];
    __syncthreads();
    float acc[8][8] = {};
    for (int k0 = ks * 512; k0 < ks * 512 + 512; k0 += 16) {
        #pragma unroll
        for (int l = 0; l < 4; l++) {
            int u = tid + l * 128;
            int k4 = u & 3, m = u >> 2;
            size_t gi = ((size_t)(i0 + m)) * 2048 + k0 + k4*4;
            float4 x = *(const float4*)&a[gi];
            float lv = ls[m];
            *(float4*)&a[gi] = make_float4(x.x - lv, x.y - lv, x.z - lv, x.w - lv);
            As[k4*4+0][m] = x.x; As[k4*4+1][m] = x.y;
            As[k4*4+2][m] = x.z; As[k4*4+3][m] = x.w;
        }
        #pragma unroll
        for (int l = 0; l < 2; l++) {
            int u = tid + l * 128;
            int d4 = u & 15, k = u >> 4;
            *(float4*)&Bs[k][d4*4] = *(const float4*)&v[(size_t)(k0 + k) * 64 + d4*4];
        }
        __syncthreads();
        #pragma unroll
        for (int k = 0; k < 16; k++) {
            float4 a0 = *(const float4*)&As[k][ty*8];
            float4 a1 = *(const float4*)&As[k][ty*8+4];
            float4 b0 = *(const float4*)&Bs[k][tx*4];
            float4 b1 = *(const float4*)&Bs[k][32 + tx*4];
            float ar[8] = {a0.x,a0.y,a0.z,a0.w,a1.x,a1.y,a1.z,a1.w};
            float br[8] = {b0.x,b0.y,b0.z,b0.w,b1.x,b1.y,b1.z,b1.w};
            #pragma unroll
            for (int i = 0; i < 8; i++)
                #pragma unroll
                for (int j = 0; j < 8; j++) acc[i][j] += ar[i] * br[j];
        }
        __syncthreads();
    }
    float* dst = ctx2 + ((size_t)ks * 8 + bh) * 2048 * 64;
    #pragma unroll
    for (int i = 0; i < 8; i++) {
        size_t rr = (size_t)(i0 + ty*8 + i) * 64;
        *(float4*)&dst[rr + tx*4]      = make_float4(acc[i][0], acc[i][1], acc[i][2], acc[i][3]);
        *(float4*)&dst[rr + 32 + tx*4] = make_float4(acc[i][4], acc[i][5], acc[i][6], acc[i][7]);
    }
}

// ---------------------------------------------------------------------------
__global__ void reduce_ctx_kernel(const float* __restrict__ ctx2,
    const float* __restrict__ lse, const float* __restrict__ colsum,
    float* __restrict__ ctx)
{
    int g = blockIdx.x * 256 + threadIdx.x;
    int elem = g * 4;
    int bh = elem >> 17;
    int i  = (elem >> 6) & 2047;
    int d  = elem & 63;
    const float4* c2 = (const float4*)ctx2;
    float4 s  = c2[g];
    float4 t1 = c2[262144 + g];
    float4 t2 = c2[524288 + g];
    float4 t3 = c2[786432 + g];
    s.x += t1.x + t2.x + t3.x; s.y += t1.y + t2.y + t3.y;
    s.z += t1.z + t2.z + t3.z; s.w += t1.w + t2.w + t3.w;
    float l = lse[bh * 2048 + i];
    float4 cs = *(const float4*)&colsum[bh * 64 + d];
    s.x -= l * cs.x; s.y -= l * cs.y; s.z -= l * cs.z; s.w -= l * cs.w;
    ((float4*)ctx)[g] = s;
}

// ---------------------------------------------------------------------------
__global__ __launch_bounds__(256) void out_kernel(
    const float* __restrict__ ctx, const float* __restrict__ Wo,
    const float* __restrict__ bo, float* __restrict__ out)
{
    __shared__ float As[16][132];
    __shared__ __align__(16) float Ws[16][128];
    const int r0 = blockIdx.x * 128, c0 = blockIdx.y * 128;
    const int tid = threadIdx.x;
    const int tx = tid & 15, ty = tid >> 4;
    float acc[8][8] = {};
    for (int k0 = 0; k0 < 128; k0 += 16) {
        #pragma unroll
        for (int l = 0; l < 2; l++) {
            int u = tid + l * 256;
            int k4 = u & 3, m = u >> 2;
            int r = r0 + m;
            int b = r >> 11, ii = r & 2047;
            int k = k0 + k4*4;
            int h = k >> 6, dd = k & 63;
            float4 xv = *(const float4*)&ctx[(((size_t)(b*2 + h)) * 2048 + ii) * 64 + dd];
            As[k4*4+0][m] = xv.x; As[k4*4+1][m] = xv.y;
            As[k4*4+2][m] = xv.z; As[k4*4+3][m] = xv.w;
        }
        #pragma unroll
        for (int l = 0; l < 2; l++) {
            int u = tid + l * 256;
            int n4 = u & 31, k = u >> 5;
            *(float4*)&Ws[k][n4*4] = *(const float4*)&Wo[(size_t)(k0 + k) * 512 + c0 + n4*4];
        }
        __syncthreads();
        #pragma unroll
        for (int k = 0; k < 16; k++) {
            float4 a0 = *(const float4*)&As[k][ty*8];
            float4 a1 = *(const float4*)&As[k][ty*8+4];
            float4 b0 = *(const float4*)&Ws[k][tx*4];
            float4 b1 = *(const float4*)&Ws[k][64 + tx*4];
            float ar[8] = {a0.x,a0.y,a0.z,a0.w,a1.x,a1.y,a1.z,a1.w};
            float br[8] = {b0.x,b0.y,b0.z,b0.w,b1.x,b1.y,b1.z,b1.w};
            #pragma unroll
            for (int i = 0; i < 8; i++)
                #pragma unroll
                for (int j = 0; j < 8; j++) acc[i][j] += ar[i] * br[j];
        }
        __syncthreads();
    }
    #pragma unroll
    for (int i = 0; i < 8; i++) {
        size_t r = (size_t)(r0 + ty*8 + i) * 512;
        #pragma unroll
        for (int half = 0; half < 2; half++) {
            int c = c0 + half*64 + tx*4;
            float4 o;
            o.x = acc[i][half*4+0] + bo[c+0];
            o.y = acc[i][half*4+1] + bo[c+1];
            o.z = acc[i][half*4+2] + bo[c+2];
            o.w = acc[i][half*4+3] + bo[c+3];
            *(float4*)&out[r + c] = o;
        }
    }
}

// ---------------------------------------------------------------------------
extern "C" void kernel_launch(void* const* d_in, const int* in_sizes, int n_in,
                              void* d_out, int out_size)
{
    const float* Q  = (const float*)d_in[0];
    const float* K  = (const float*)d_in[1];
    const float* V  = (const float*)d_in[2];
    const int*   mask = (const int*)d_in[3];   // bool -> int32 in harness
    const float* Wq = (const float*)d_in[4];
    const float* bq = (const float*)d_in[5];
    const float* Wk = (const float*)d_in[6];
    const float* bk = (const float*)d_in[7];
    const float* Wv = (const float*)d_in[8];
    const float* bv = (const float*)d_in[9];
    const float* Wo = (const float*)d_in[10];
    const float* bo = (const float*)d_in[11];

    float* out  = (float*)d_out;                      // [B, L, 512]
    float* attn = out + (size_t)4 * 2048 * 512;       // [B, H, L, L]

    float *gv, *gctx, *gctx2, *gse, *gcs;
    __nv_bfloat16 *qh, *ql, *kh, *kl;
    cudaGetSymbolAddress((void**)&gv,    g_v);
    cudaGetSymbolAddress((void**)&gctx,  g_ctx);
    cudaGetSymbolAddress((void**)&gctx2, g_ctx2);
    cudaGetSymbolAddress((void**)&gse,   g_sumexp);
    cudaGetSymbolAddress((void**)&gcs,   g_colsum);
    cudaGetSymbolAddress((void**)&qh,    g_qh);
    cudaGetSymbolAddress((void**)&ql,    g_ql);
    cudaGetSymbolAddress((void**)&kh,    g_kh);
    cudaGetSymbolAddress((void**)&kl,    g_kl);

    static int smem_set = 0;
    if (!smem_set) {
        cudaFuncSetAttribute(scores_mma_kernel, cudaFuncAttributeMaxDynamicSharedMemorySize, 74240);
        smem_set = 1;
    }

    zero_kernel<<<17, 256>>>(gse, gcs);
    proj3_kernel<<<dim3(64, 3), 256>>>(Q, K, V, Wq, bq, Wk, bk, Wv, bv, qh, ql, kh, kl, gv);
    colsum_kernel<<<dim3(8, 8), 256>>>(gv, gcs);
    scores_mma_kernel<<<dim3(16, 16, 8), 256, 74240>>>(qh, ql, kh, kl, mask, attn, gse);
    lse_kernel<<<16, 256>>>(gse);
    av_kernel<<<dim3(16, 4, 8), 128>>>(attn, gv, gse, gctx2);
    reduce_ctx_kernel<<<1024, 256>>>(gctx2, gse, gcs, gctx);
    out_kernel<<<dim3(64, 4), 256>>>(gctx, Wo, bo, out);
}

// round 6
// speedup vs baseline: 1.4517x; 1.0367x over previous
#include <cuda_runtime.h>
#include <cuda_bf16.h>
#include <math.h>
#include <stdint.h>

#define Lseq 2048
#define BHn  8

// scratch (allocation-free rule: __device__ globals)
__device__ float g_v[BHn * Lseq * 64];
__device__ float g_ctx[BHn * Lseq * 64];
__device__ float g_sumexp[BHn * Lseq];          // sumexp -> lse (in place)
__device__ float g_colsum[BHn * 64];            // per-(bh) column sums of v
__device__ __nv_bfloat16 g_qh[BHn * Lseq * 64];
__device__ __nv_bfloat16 g_ql[BHn * Lseq * 64];
__device__ __nv_bfloat16 g_kh[BHn * Lseq * 64];
__device__ __nv_bfloat16 g_kl[BHn * Lseq * 64];
__device__ __nv_bfloat16 g_wth[3 * 128 * 512];  // W^T hi  [which][n][k]
__device__ __nv_bfloat16 g_wtl[3 * 128 * 512];  // W^T lo
__device__ __nv_bfloat16 g_vth[BHn * 64 * Lseq]; // V^T hi [bh][d][j]
__device__ __nv_bfloat16 g_vtl[BHn * 64 * Lseq]; // V^T lo

__device__ __forceinline__ uint32_t smem_u32(const void* p) {
    uint32_t a;
    asm("{ .reg .u64 t; cvta.to.shared.u64 t, %1; cvt.u32.u64 %0, t; }" : "=r"(a) : "l"(p));
    return a;
}
__device__ __forceinline__ void ldsm_x4(uint32_t* r, uint32_t addr) {
    asm volatile("ldmatrix.sync.aligned.m8n8.x4.shared.b16 {%0,%1,%2,%3}, [%4];"
        : "=r"(r[0]), "=r"(r[1]), "=r"(r[2]), "=r"(r[3]) : "r"(addr));
}
__device__ __forceinline__ void mma_bf16(float* c, const uint32_t* a, const uint32_t* b) {
    asm volatile("mma.sync.aligned.m16n8k16.row.col.f32.bf16.bf16.f32 "
        "{%0,%1,%2,%3}, {%4,%5,%6,%7}, {%8,%9}, {%0,%1,%2,%3};"
        : "+f"(c[0]), "+f"(c[1]), "+f"(c[2]), "+f"(c[3])
        : "r"(a[0]), "r"(a[1]), "r"(a[2]), "r"(a[3]), "r"(b[0]), "r"(b[1]));
}
__device__ __forceinline__ uint32_t pack_bf2(float a, float b) {
    __nv_bfloat162 t;
    t.x = __float2bfloat16(a); t.y = __float2bfloat16(b);
    return *(uint32_t*)&t;
}
// split float4 -> hi uint2 (4 bf16) and lo uint2
__device__ __forceinline__ void split4(float4 x, uint2* hi, uint2* lo) {
    __nv_bfloat16 hx = __float2bfloat16(x.x), hy = __float2bfloat16(x.y);
    __nv_bfloat16 hz = __float2bfloat16(x.z), hw = __float2bfloat16(x.w);
    __nv_bfloat162 h01; h01.x = hx; h01.y = hy;
    __nv_bfloat162 h23; h23.x = hz; h23.y = hw;
    hi->x = *(uint32_t*)&h01; hi->y = *(uint32_t*)&h23;
    __nv_bfloat162 l01, l23;
    l01.x = __float2bfloat16(x.x - __bfloat162float(hx));
    l01.y = __float2bfloat16(x.y - __bfloat162float(hy));
    l23.x = __float2bfloat16(x.z - __bfloat162float(hz));
    l23.y = __float2bfloat16(x.w - __bfloat162float(hw));
    lo->x = *(uint32_t*)&l01; lo->y = *(uint32_t*)&l23;
}

// ---------------------------------------------------------------------------
__global__ void zero_kernel(float* __restrict__ sumexp, float* __restrict__ colsum)
{
    if (blockIdx.x < 16) {
        int g = blockIdx.x * 256 + threadIdx.x;
        ((float4*)sumexp)[g] = make_float4(0.f, 0.f, 0.f, 0.f);
    } else if (threadIdx.x < 128) {
        ((float4*)colsum)[threadIdx.x] = make_float4(0.f, 0.f, 0.f, 0.f);
    }
}

// ---------------------------------------------------------------------------
// Weight prep: W [512][128] fp32 -> W^T hi/lo bf16 [which][128 n][512 k].
// grid (16 kchunks, 3 which), 128 thr.
// ---------------------------------------------------------------------------
__global__ void wt_kernel(const float* __restrict__ Wq, const float* __restrict__ Wk,
                          const float* __restrict__ Wv,
                          __nv_bfloat16* __restrict__ wth, __nv_bfloat16* __restrict__ wtl)
{
    __shared__ float sm[32][132];
    const int which = blockIdx.y;
    const float* W = which == 0 ? Wq : (which == 1 ? Wk : Wv);
    const int k0 = blockIdx.x * 32;
    const int t = threadIdx.x;
    #pragma unroll
    for (int l = 0; l < 8; l++) {
        int u = t + l * 128;
        int k = u >> 5, n4 = u & 31;
        float4 w = *(const float4*)&W[(size_t)(k0 + k) * 128 + n4 * 4];
        sm[k][n4*4+0] = w.x; sm[k][n4*4+1] = w.y;
        sm[k][n4*4+2] = w.z; sm[k][n4*4+3] = w.w;
    }
    __syncthreads();
    uint32_t hw[16], lw[16];
    #pragma unroll
    for (int kk = 0; kk < 32; kk += 2) {
        float a = sm[kk][t], b = sm[kk+1][t];
        __nv_bfloat16 ha = __float2bfloat16(a), hb = __float2bfloat16(b);
        hw[kk>>1] = pack_bf2(a, b);
        lw[kk>>1] = pack_bf2(a - __bfloat162float(ha), b - __bfloat162float(hb));
    }
    size_t base = ((size_t)which * 128 + t) * 512 + k0;
    #pragma unroll
    for (int s = 0; s < 4; s++) {
        *(uint4*)&wth[base + s*8] = *(uint4*)&hw[s*4];
        *(uint4*)&wtl[base + s*8] = *(uint4*)&lw[s*4];
    }
}

// ---------------------------------------------------------------------------
// QKV projection via mma.sync bf16 3-term split. M=8192, K=512, N=128.
// CTA 128x128, 8 warps (4m x 2n), warp 32x64.
// ---------------------------------------------------------------------------
__global__ __launch_bounds__(256, 2) void proj_mma_kernel(
    const float* __restrict__ Q, const float* __restrict__ K, const float* __restrict__ V,
    const __nv_bfloat16* __restrict__ wth, const __nv_bfloat16* __restrict__ wtl,
    const float* __restrict__ bq, const float* __restrict__ bk, const float* __restrict__ bv,
    __nv_bfloat16* __restrict__ qh, __nv_bfloat16* __restrict__ ql,
    __nv_bfloat16* __restrict__ kh, __nv_bfloat16* __restrict__ kl,
    float* __restrict__ gv)
{
    extern __shared__ char smem[];
    const int which = blockIdx.y;
    const float* X    = which == 0 ? Q  : (which == 1 ? K  : V);
    const float* bias = which == 0 ? bq : (which == 1 ? bk : bv);
    const int r0 = blockIdx.x * 128;
    const int tid = threadIdx.x, wid = tid >> 5, lid = tid & 31;
    const int wm = wid & 3, wn = wid >> 2;

    char* tXH = smem;              // 128 rows x 144B
    char* tXL = smem + 18432;
    char* tWH = smem + 36864;      // 128 n-rows x 144B
    char* tWL = smem + 55296;
    const uint32_t sXH = smem_u32(tXH), sXL = smem_u32(tXL);
    const uint32_t sWH = smem_u32(tWH), sWL = smem_u32(tWL);

    const uint32_t aOff = (uint32_t)((wm * 32 + (lid & 15)) * 144 + ((lid >> 4) << 4));
    const uint32_t bOff = (uint32_t)((wn * 64 + ((lid & 16) >> 1) + (lid & 7)) * 144
                                     + ((lid & 8) << 1));
    float acc[2][8][4] = {};

    for (int k0 = 0; k0 < 512; k0 += 64) {
        // X tile 128x64 f32 -> bf16 hi/lo
        #pragma unroll
        for (int l = 0; l < 8; l++) {
            int u = tid + l * 256;
            int row = u >> 4, k4 = u & 15;
            float4 x = *(const float4*)&X[(size_t)(r0 + row) * 512 + k0 + k4 * 4];
            uint2 hi, lo; split4(x, &hi, &lo);
            *(uint2*)(tXH + row * 144 + k4 * 8) = hi;
            *(uint2*)(tXL + row * 144 + k4 * 8) = lo;
        }
        // W^T tiles 128x64 bf16 (pre-split)
        #pragma unroll
        for (int l = 0; l < 4; l++) {
            int u = tid + l * 256;
            int n = u >> 3, c = u & 7;
            size_t gidx = ((size_t)which * 128 + n) * 512 + k0 + c * 8;
            *(float4*)(tWH + n * 144 + c * 16) = *(const float4*)&wth[gidx];
            *(float4*)(tWL + n * 144 + c * 16) = *(const float4*)&wtl[gidx];
        }
        __syncthreads();

        const uint32_t qb[3] = { sXH, sXH, sXL };
        const uint32_t kb[3] = { sWH, sWL, sWH };
        #pragma unroll
        for (int t = 0; t < 3; t++) {
            const uint32_t qa = qb[t] + aOff;
            const uint32_t ka = kb[t] + bOff;
            #pragma unroll
            for (int ks = 0; ks < 4; ks++) {
                uint32_t af[2][4], bf[4][4];
                ldsm_x4(af[0], qa + ks * 32);
                ldsm_x4(af[1], qa + ks * 32 + 16 * 144);
                #pragma unroll
                for (int np = 0; np < 4; np++)
                    ldsm_x4(bf[np], ka + ks * 32 + np * 16 * 144);
                #pragma unroll
                for (int mi = 0; mi < 2; mi++)
                    #pragma unroll
                    for (int np = 0; np < 4; np++) {
                        mma_bf16(acc[mi][np*2],   af[mi], &bf[np][0]);
                        mma_bf16(acc[mi][np*2+1], af[mi], &bf[np][2]);
                    }
            }
        }
        __syncthreads();
    }

    // epilogue: +bias, split to bf16 h/l (q/k) or fp32 (v)
    const int g = lid >> 2, qid = lid & 3;
    #pragma unroll
    for (int mi = 0; mi < 2; mi++) {
        #pragma unroll
        for (int half = 0; half < 2; half++) {
            int r = r0 + wm * 32 + mi * 16 + half * 8 + g;
            int b = r >> 11, ii = r & 2047;
            #pragma unroll
            for (int ni = 0; ni < 8; ni++) {
                int col = wn * 64 + ni * 8 + qid * 2;
                float v0 = acc[mi][ni][half*2+0] + bias[col];
                float v1 = acc[mi][ni][half*2+1] + bias[col+1];
                int h = col >> 6, dd = col & 63;
                size_t idx = (((size_t)(b*2 + h)) * 2048 + ii) * 64 + dd;
                if (which == 2) {
                    *(float2*)&gv[idx] = make_float2(v0, v1);
                } else {
                    __nv_bfloat16 h0 = __float2bfloat16(v0), h1 = __float2bfloat16(v1);
                    uint32_t hp = pack_bf2(v0, v1);
                    uint32_t lp = pack_bf2(v0 - __bfloat162float(h0), v1 - __bfloat162float(h1));
                    __nv_bfloat16* ph = (which == 0 ? qh : kh);
                    __nv_bfloat16* pl = (which == 0 ? ql : kl);
                    *(uint32_t*)&ph[idx] = hp;
                    *(uint32_t*)&pl[idx] = lp;
                }
            }
        }
    }
}

// ---------------------------------------------------------------------------
// V transpose + split: v [bh][j][d] fp32 -> vt hi/lo bf16 [bh][d][j].
// grid (16 jchunks, 8 bh), 256 thr.
// ---------------------------------------------------------------------------
__global__ void vt_kernel(const float* __restrict__ gv,
                          __nv_bfloat16* __restrict__ vth, __nv_bfloat16* __restrict__ vtl)
{
    __shared__ float sm[128][68];
    const int bh = blockIdx.y;
    const int j0 = blockIdx.x * 128;
    const int tid = threadIdx.x;
    const float* v = gv + (size_t)bh * 2048 * 64;
    #pragma unroll
    for (int l = 0; l < 8; l++) {
        int u = tid + l * 256;
        int j = u >> 4, d4 = u & 15;
        float4 x = *(const float4*)&v[(size_t)(j0 + j) * 64 + d4 * 4];
        sm[j][d4*4+0] = x.x; sm[j][d4*4+1] = x.y;
        sm[j][d4*4+2] = x.z; sm[j][d4*4+3] = x.w;
    }
    __syncthreads();
    #pragma unroll
    for (int l = 0; l < 8; l++) {
        int u = tid + l * 256;
        int d = u >> 5, j4 = u & 31;
        float4 x = make_float4(sm[j4*4+0][d], sm[j4*4+1][d], sm[j4*4+2][d], sm[j4*4+3][d]);
        uint2 hi, lo; split4(x, &hi, &lo);
        size_t idx = ((size_t)bh * 64 + d) * 2048 + j0 + j4 * 4;
        *(uint2*)&vth[idx] = hi;
        *(uint2*)&vtl[idx] = lo;
    }
}

// ---------------------------------------------------------------------------
__global__ void colsum_kernel(const float* __restrict__ gv, float* __restrict__ colsum)
{
    __shared__ float red[256];
    const int bh = blockIdx.x;
    const int tid = threadIdx.x;
    const int c = tid & 63, p = tid >> 6;
    const float* v = gv + (size_t)bh * 2048 * 64;
    int jb = blockIdx.y * 256 + p * 64;
    float s = 0.f;
    #pragma unroll 8
    for (int j = 0; j < 64; j++) s += v[(size_t)(jb + j) * 64 + c];
    red[tid] = s;
    __syncthreads();
    if (tid < 64)
        atomicAdd(&colsum[bh * 64 + c], red[tid] + red[tid+64] + red[tid+128] + red[tid+192]);
}

// ---------------------------------------------------------------------------
// mma.sync scores (unchanged from round 5).
// ---------------------------------------------------------------------------
__global__ __launch_bounds__(256, 2) void scores_mma_kernel(
    const __nv_bfloat16* __restrict__ gqh, const __nv_bfloat16* __restrict__ gql,
    const __nv_bfloat16* __restrict__ gkh, const __nv_bfloat16* __restrict__ gkl,
    const int* __restrict__ mask, float* __restrict__ attn, float* __restrict__ sumexp)
{
    extern __shared__ char smem[];
    const int tid = threadIdx.x, wid = tid >> 5, lid = tid & 31;
    const int bh = blockIdx.z, b = bh >> 1;
    const int i0 = blockIdx.x * 128, j0 = blockIdx.y * 128;
    const int wm = wid & 3, wn = wid >> 2;

    char* tQH = smem;
    char* tQL = smem + 18432;
    char* tKH = smem + 36864;
    char* tKL = smem + 55296;
    int*  smk = (int*)(smem + 73728);

    {
        const float4* s0 = (const float4*)(gqh + ((size_t)bh * 2048 + i0) * 64);
        const float4* s1 = (const float4*)(gql + ((size_t)bh * 2048 + i0) * 64);
        const float4* s2 = (const float4*)(gkh + ((size_t)bh * 2048 + j0) * 64);
        const float4* s3 = (const float4*)(gkl + ((size_t)bh * 2048 + j0) * 64);
        #pragma unroll
        for (int l = 0; l < 4; l++) {
            int u = tid + l * 256;
            int row = u >> 3, ch = u & 7;
            int off = row * 144 + ch * 16;
            *(float4*)(tQH + off) = s0[u];
            *(float4*)(tQL + off) = s1[u];
            *(float4*)(tKH + off) = s2[u];
            *(float4*)(tKL + off) = s3[u];
        }
    }
    if (tid < 128) smk[tid] = mask[b * 2048 + j0 + tid];
    __syncthreads();

    const uint32_t aOff = (uint32_t)((wm * 32 + (lid & 15)) * 144 + ((lid >> 4) << 4));
    const uint32_t bOff = (uint32_t)((wn * 64 + ((lid & 16) >> 1) + (lid & 7)) * 144
                                     + ((lid & 8) << 1));

    float acc[2][8][4] = {};
    const uint32_t qb[3] = { smem_u32(tQH), smem_u32(tQH), smem_u32(tQL) };
    const uint32_t kb[3] = { smem_u32(tKH), smem_u32(tKL), smem_u32(tKH) };

    #pragma unroll
    for (int t = 0; t < 3; t++) {
        const uint32_t qa = qb[t] + aOff;
        const uint32_t ka = kb[t] + bOff;
        #pragma unroll
        for (int ks = 0; ks < 4; ks++) {
            uint32_t af[2][4], bf[4][4];
            ldsm_x4(af[0], qa + ks * 32);
            ldsm_x4(af[1], qa + ks * 32 + 16 * 144);
            #pragma unroll
            for (int np = 0; np < 4; np++)
                ldsm_x4(bf[np], ka + ks * 32 + np * 16 * 144);
            #pragma unroll
            for (int mi = 0; mi < 2; mi++)
                #pragma unroll
                for (int np = 0; np < 4; np++) {
                    mma_bf16(acc[mi][np*2],   af[mi], &bf[np][0]);
                    mma_bf16(acc[mi][np*2+1], af[mi], &bf[np][2]);
                }
        }
    }
    __syncthreads();

    float* buf = (float*)smem;             // [128][132]
    const int g = lid >> 2, qid = lid & 3;
    float rs[2][2] = {};
    #pragma unroll
    for (int mi = 0; mi < 2; mi++) {
        const int row0 = wm * 32 + mi * 16 + g;
        #pragma unroll
        for (int ni = 0; ni < 8; ni++) {
            const int col = wn * 64 + ni * 8 + qid * 2;
            const int m0 = smk[col], m1 = smk[col + 1];
            float v0 = acc[mi][ni][0], v1 = acc[mi][ni][1];
            float v2 = acc[mi][ni][2], v3 = acc[mi][ni][3];
            v0 = 10.0f - 20.0f / (__expf(v0 * 0.25f) + 1.0f);
            v1 = 10.0f - 20.0f / (__expf(v1 * 0.25f) + 1.0f);
            v2 = 10.0f - 20.0f / (__expf(v2 * 0.25f) + 1.0f);
            v3 = 10.0f - 20.0f / (__expf(v3 * 0.25f) + 1.0f);
            if (m0) { v0 = -10.0f; v2 = -10.0f; }
            if (m1) { v1 = -10.0f; v3 = -10.0f; }
            rs[mi][0] += __expf(v0) + __expf(v1);
            rs[mi][1] += __expf(v2) + __expf(v3);
            *(float2*)&buf[row0 * 132 + col]       = make_float2(v0, v1);
            *(float2*)&buf[(row0 + 8) * 132 + col] = make_float2(v2, v3);
        }
    }
    #pragma unroll
    for (int mi = 0; mi < 2; mi++)
        #pragma unroll
        for (int hl = 0; hl < 2; hl++) {
            float r = rs[mi][hl];
            r += __shfl_xor_sync(0xffffffffu, r, 1);
            r += __shfl_xor_sync(0xffffffffu, r, 2);
            if (qid == 0)
                atomicAdd(&sumexp[bh * 2048 + i0 + wm * 32 + mi * 16 + hl * 8 + g], r);
        }
    __syncthreads();

    #pragma unroll
    for (int l = 0; l < 16; l++) {
        int idx = tid + l * 256;
        int row = idx >> 5, c4 = idx & 31;
        float4 v = *(const float4*)&buf[row * 132 + c4 * 4];
        *(float4*)(attn + ((size_t)bh * 2048 + i0 + row) * 2048 + j0 + c4 * 4) = v;
    }
}

// ---------------------------------------------------------------------------
__global__ void lse_kernel(float* __restrict__ sumexp)
{
    int g = blockIdx.x * 256 + threadIdx.x;
    float4 v = ((float4*)sumexp)[g];
    v.x = __logf(v.x); v.y = __logf(v.y); v.z = __logf(v.z); v.w = __logf(v.w);
    ((float4*)sumexp)[g] = v;
}

// ---------------------------------------------------------------------------
// AV via mma.sync bf16 3-term: ctx[i][d] = sum_j x[i][j] vt[d][j] - lse[i]*colsum[d]
// + fused normalize write-back (attn -> x - lse). CTA: 128 i x 64 d, K chunks 64.
// ---------------------------------------------------------------------------
__global__ __launch_bounds__(256, 2) void av_mma_kernel(
    float* __restrict__ attn,
    const __nv_bfloat16* __restrict__ vth, const __nv_bfloat16* __restrict__ vtl,
    const float* __restrict__ lse, const float* __restrict__ colsum,
    float* __restrict__ ctx)
{
    extern __shared__ char smem[];
    const int bh = blockIdx.y;
    const int i0 = blockIdx.x * 128;
    const int tid = threadIdx.x, wid = tid >> 5, lid = tid & 31;
    const int wm = wid & 3, wn = wid >> 2;

    char* tAH = smem;               // 128 x 144B
    char* tAL = smem + 18432;
    char* tBH = smem + 36864;       // 64 x 144B
    char* tBL = smem + 46080;
    float* ls = (float*)(smem + 55296);   // 128
    float* cs = (float*)(smem + 55808);   // 64
    const uint32_t sAH = smem_u32(tAH), sAL = smem_u32(tAL);
    const uint32_t sBH = smem_u32(tBH), sBL = smem_u32(tBL);

    if (tid < 128) ls[tid] = lse[bh * 2048 + i0 + tid];
    else if (tid < 192) cs[tid - 128] = colsum[bh * 64 + (tid - 128)];
    __syncthreads();

    float* a = attn + (size_t)bh * 2048 * 2048;
    const __nv_bfloat16* bh_vt = vth + (size_t)bh * 64 * 2048;
    const __nv_bfloat16* bl_vt = vtl + (size_t)bh * 64 * 2048;

    const uint32_t aOff = (uint32_t)((wm * 32 + (lid & 15)) * 144 + ((lid >> 4) << 4));
    const uint32_t bOff = (uint32_t)((wn * 32 + ((lid & 16) >> 1) + (lid & 7)) * 144
                                     + ((lid & 8) << 1));
    float acc[2][4][4] = {};

    for (int k0 = 0; k0 < 2048; k0 += 64) {
        // A tile: attn fp32 128x64, write back x-lse, split to bf16 hi/lo
        #pragma unroll
        for (int l = 0; l < 8; l++) {
            int u = tid + l * 256;
            int row = u >> 4, j4 = u & 15;
            size_t gi = (size_t)(i0 + row) * 2048 + k0 + j4 * 4;
            float4 x = *(const float4*)&a[gi];
            float lv = ls[row];
            *(float4*)&a[gi] = make_float4(x.x - lv, x.y - lv, x.z - lv, x.w - lv);
            uint2 hi, lo; split4(x, &hi, &lo);
            *(uint2*)(tAH + row * 144 + j4 * 8) = hi;
            *(uint2*)(tAL + row * 144 + j4 * 8) = lo;
        }
        // B tiles: vt bf16 64x64
        #pragma unroll
        for (int l = 0; l < 2; l++) {
            int u = tid + l * 256;
            int d = u >> 3, c = u & 7;
            size_t gidx = (size_t)d * 2048 + k0 + c * 8;
            *(float4*)(tBH + d * 144 + c * 16) = *(const float4*)&bh_vt[gidx];
            *(float4*)(tBL + d * 144 + c * 16) = *(const float4*)&bl_vt[gidx];
        }
        __syncthreads();

        #pragma unroll
        for (int ks = 0; ks < 4; ks++) {
            uint32_t ah[2][4], al[2][4], bhf[2][4], blf[2][4];
            ldsm_x4(ah[0], sAH + aOff + ks * 32);
            ldsm_x4(ah[1], sAH + aOff + ks * 32 + 16 * 144);
            ldsm_x4(al[0], sAL + aOff + ks * 32);
            ldsm_x4(al[1], sAL + aOff + ks * 32 + 16 * 144);
            ldsm_x4(bhf[0], sBH + bOff + ks * 32);
            ldsm_x4(bhf[1], sBH + bOff + ks * 32 + 16 * 144);
            ldsm_x4(blf[0], sBL + bOff + ks * 32);
            ldsm_x4(blf[1], sBL + bOff + ks * 32 + 16 * 144);
            #pragma unroll
            for (int mi = 0; mi < 2; mi++)
                #pragma unroll
                for (int n2 = 0; n2 < 2; n2++)
                    #pragma unroll
                    for (int p = 0; p < 2; p++) {
                        float* c = acc[mi][n2*2+p];
                        mma_bf16(c, ah[mi], &bhf[n2][p*2]);
                        mma_bf16(c, ah[mi], &blf[n2][p*2]);
                        mma_bf16(c, al[mi], &bhf[n2][p*2]);
                    }
        }
        __syncthreads();
    }

    // epilogue: -lse*colsum correction, write ctx fp32
    const int g = lid >> 2, qid = lid & 3;
    #pragma unroll
    for (int mi = 0; mi < 2; mi++) {
        #pragma unroll
        for (int half = 0; half < 2; half++) {
            int rl = wm * 32 + mi * 16 + half * 8 + g;
            float lv = ls[rl];
            size_t rbase = ((size_t)bh * 2048 + i0 + rl) * 64;
            #pragma unroll
            for (int ni = 0; ni < 4; ni++) {
                int col = wn * 32 + ni * 8 + qid * 2;
                float v0 = acc[mi][ni][half*2+0] - lv * cs[col];
                float v1 = acc[mi][ni][half*2+1] - lv * cs[col+1];
                *(float2*)&ctx[rbase + col] = make_float2(v0, v1);
            }
        }
    }
}

// ---------------------------------------------------------------------------
__global__ __launch_bounds__(256) void out_kernel(
    const float* __restrict__ ctx, const float* __restrict__ Wo,
    const float* __restrict__ bo, float* __restrict__ out)
{
    __shared__ float As[16][132];
    __shared__ __align__(16) float Ws[16][128];
    const int r0 = blockIdx.x * 128, c0 = blockIdx.y * 128;
    const int tid = threadIdx.x;
    const int tx = tid & 15, ty = tid >> 4;
    float acc[8][8] = {};
    for (int k0 = 0; k0 < 128; k0 += 16) {
        #pragma unroll
        for (int l = 0; l < 2; l++) {
            int u = tid + l * 256;
            int k4 = u & 3, m = u >> 2;
            int r = r0 + m;
            int b = r >> 11, ii = r & 2047;
            int k = k0 + k4*4;
            int h = k >> 6, dd = k & 63;
            float4 xv = *(const float4*)&ctx[(((size_t)(b*2 + h)) * 2048 + ii) * 64 + dd];
            As[k4*4+0][m] = xv.x; As[k4*4+1][m] = xv.y;
            As[k4*4+2][m] = xv.z; As[k4*4+3][m] = xv.w;
        }
        #pragma unroll
        for (int l = 0; l < 2; l++) {
            int u = tid + l * 256;
            int n4 = u & 31, k = u >> 5;
            *(float4*)&Ws[k][n4*4] = *(const float4*)&Wo[(size_t)(k0 + k) * 512 + c0 + n4*4];
        }
        __syncthreads();
        #pragma unroll
        for (int k = 0; k < 16; k++) {
            float4 a0 = *(const float4*)&As[k][ty*8];
            float4 a1 = *(const float4*)&As[k][ty*8+4];
            float4 b0 = *(const float4*)&Ws[k][tx*4];
            float4 b1 = *(const float4*)&Ws[k][64 + tx*4];
            float ar[8] = {a0.x,a0.y,a0.z,a0.w,a1.x,a1.y,a1.z,a1.w};
            float br[8] = {b0.x,b0.y,b0.z,b0.w,b1.x,b1.y,b1.z,b1.w};
            #pragma unroll
            for (int i = 0; i < 8; i++)
                #pragma unroll
                for (int j = 0; j < 8; j++) acc[i][j] += ar[i] * br[j];
        }
        __syncthreads();
    }
    #pragma unroll
    for (int i = 0; i < 8; i++) {
        size_t r = (size_t)(r0 + ty*8 + i) * 512;
        #pragma unroll
        for (int half = 0; half < 2; half++) {
            int c = c0 + half*64 + tx*4;
            float4 o;
            o.x = acc[i][half*4+0] + bo[c+0];
            o.y = acc[i][half*4+1] + bo[c+1];
            o.z = acc[i][half*4+2] + bo[c+2];
            o.w = acc[i][half*4+3] + bo[c+3];
            *(float4*)&out[r + c] = o;
        }
    }
}

// ---------------------------------------------------------------------------
extern "C" void kernel_launch(void* const* d_in, const int* in_sizes, int n_in,
                              void* d_out, int out_size)
{
    const float* Q  = (const float*)d_in[0];
    const float* K  = (const float*)d_in[1];
    const float* V  = (const float*)d_in[2];
    const int*   mask = (const int*)d_in[3];   // bool -> int32 in harness
    const float* Wq = (const float*)d_in[4];
    const float* bq = (const float*)d_in[5];
    const float* Wk = (const float*)d_in[6];
    const float* bk = (const float*)d_in[7];
    const float* Wv = (const float*)d_in[8];
    const float* bv = (const float*)d_in[9];
    const float* Wo = (const float*)d_in[10];
    const float* bo = (const float*)d_in[11];

    float* out  = (float*)d_out;                      // [B, L, 512]
    float* attn = out + (size_t)4 * 2048 * 512;       // [B, H, L, L]

    float *gv, *gctx, *gse, *gcs;
    __nv_bfloat16 *qh, *ql, *kh, *kl, *wth, *wtl, *vth, *vtl;
    cudaGetSymbolAddress((void**)&gv,   g_v);
    cudaGetSymbolAddress((void**)&gctx, g_ctx);
    cudaGetSymbolAddress((void**)&gse,  g_sumexp);
    cudaGetSymbolAddress((void**)&gcs,  g_colsum);
    cudaGetSymbolAddress((void**)&qh,   g_qh);
    cudaGetSymbolAddress((void**)&ql,   g_ql);
    cudaGetSymbolAddress((void**)&kh,   g_kh);
    cudaGetSymbolAddress((void**)&kl,   g_kl);
    cudaGetSymbolAddress((void**)&wth,  g_wth);
    cudaGetSymbolAddress((void**)&wtl,  g_wtl);
    cudaGetSymbolAddress((void**)&vth,  g_vth);
    cudaGetSymbolAddress((void**)&vtl,  g_vtl);

    static int smem_set = 0;
    if (!smem_set) {
        cudaFuncSetAttribute(scores_mma_kernel, cudaFuncAttributeMaxDynamicSharedMemorySize, 74240);
        cudaFuncSetAttribute(proj_mma_kernel,   cudaFuncAttributeMaxDynamicSharedMemorySize, 73728);
        cudaFuncSetAttribute(av_mma_kernel,     cudaFuncAttributeMaxDynamicSharedMemorySize, 56064);
        smem_set = 1;
    }

    zero_kernel<<<17, 256>>>(gse, gcs);
    wt_kernel<<<dim3(16, 3), 128>>>(Wq, Wk, Wv, wth, wtl);
    proj_mma_kernel<<<dim3(64, 3), 256, 73728>>>(Q, K, V, wth, wtl, bq, bk, bv,
                                                 qh, ql, kh, kl, gv);
    colsum_kernel<<<dim3(8, 8), 256>>>(gv, gcs);
    vt_kernel<<<dim3(16, 8), 256>>>(gv, vth, vtl);
    scores_mma_kernel<<<dim3(16, 16, 8), 256, 74240>>>(qh, ql, kh, kl, mask, attn, gse);
    lse_kernel<<<16, 256>>>(gse);
    av_mma_kernel<<<dim3(16, 8), 256, 56064>>>(attn, vth, vtl, gse, gcs, gctx);
    out_kernel<<<dim3(64, 4), 256>>>(gctx, Wo, bo, out);
}

// round 7
// speedup vs baseline: 1.8015x; 1.2410x over previous
#include <cuda_runtime.h>
#include <cuda_bf16.h>
#include <math.h>
#include <stdint.h>

#define Lseq 2048
#define BHn  8

// scratch (allocation-free rule: __device__ globals)
__device__ float g_v[BHn * Lseq * 64];
__device__ float g_ctx[BHn * Lseq * 64];
__device__ float g_ctx2[4 * BHn * Lseq * 64];   // k-split partials
__device__ float g_sumexp[BHn * Lseq];          // sumexp -> lse (in place)
__device__ float g_colsum[BHn * 64];            // per-(bh) column sums of v
__device__ __nv_bfloat16 g_qh[BHn * Lseq * 64];
__device__ __nv_bfloat16 g_ql[BHn * Lseq * 64];
__device__ __nv_bfloat16 g_kh[BHn * Lseq * 64];
__device__ __nv_bfloat16 g_kl[BHn * Lseq * 64];
__device__ __nv_bfloat16 g_wth[3 * 128 * 512];  // W^T hi  [which][n][k]
__device__ __nv_bfloat16 g_wtl[3 * 128 * 512];  // W^T lo
__device__ __nv_bfloat16 g_vth[BHn * 64 * Lseq]; // V^T hi [bh][d][j]
__device__ __nv_bfloat16 g_vtl[BHn * 64 * Lseq]; // V^T lo

__device__ __forceinline__ uint32_t smem_u32(const void* p) {
    uint32_t a;
    asm("{ .reg .u64 t; cvta.to.shared.u64 t, %1; cvt.u32.u64 %0, t; }" : "=r"(a) : "l"(p));
    return a;
}
__device__ __forceinline__ void ldsm_x4(uint32_t* r, uint32_t addr) {
    asm volatile("ldmatrix.sync.aligned.m8n8.x4.shared.b16 {%0,%1,%2,%3}, [%4];"
        : "=r"(r[0]), "=r"(r[1]), "=r"(r[2]), "=r"(r[3]) : "r"(addr));
}
__device__ __forceinline__ void mma_bf16(float* c, const uint32_t* a, const uint32_t* b) {
    asm volatile("mma.sync.aligned.m16n8k16.row.col.f32.bf16.bf16.f32 "
        "{%0,%1,%2,%3}, {%4,%5,%6,%7}, {%8,%9}, {%0,%1,%2,%3};"
        : "+f"(c[0]), "+f"(c[1]), "+f"(c[2]), "+f"(c[3])
        : "r"(a[0]), "r"(a[1]), "r"(a[2]), "r"(a[3]), "r"(b[0]), "r"(b[1]));
}
__device__ __forceinline__ uint32_t pack_bf2(float a, float b) {
    __nv_bfloat162 t;
    t.x = __float2bfloat16(a); t.y = __float2bfloat16(b);
    return *(uint32_t*)&t;
}
// split float4 -> hi uint2 (4 bf16) and lo uint2
__device__ __forceinline__ void split4(float4 x, uint2* hi, uint2* lo) {
    __nv_bfloat16 hx = __float2bfloat16(x.x), hy = __float2bfloat16(x.y);
    __nv_bfloat16 hz = __float2bfloat16(x.z), hw = __float2bfloat16(x.w);
    __nv_bfloat162 h01; h01.x = hx; h01.y = hy;
    __nv_bfloat162 h23; h23.x = hz; h23.y = hw;
    hi->x = *(uint32_t*)&h01; hi->y = *(uint32_t*)&h23;
    __nv_bfloat162 l01, l23;
    l01.x = __float2bfloat16(x.x - __bfloat162float(hx));
    l01.y = __float2bfloat16(x.y - __bfloat162float(hy));
    l23.x = __float2bfloat16(x.z - __bfloat162float(hz));
    l23.y = __float2bfloat16(x.w - __bfloat162float(hw));
    lo->x = *(uint32_t*)&l01; lo->y = *(uint32_t*)&l23;
}

// ---------------------------------------------------------------------------
__global__ void zero_kernel(float* __restrict__ sumexp, float* __restrict__ colsum)
{
    if (blockIdx.x < 16) {
        int g = blockIdx.x * 256 + threadIdx.x;
        ((float4*)sumexp)[g] = make_float4(0.f, 0.f, 0.f, 0.f);
    } else if (threadIdx.x < 128) {
        ((float4*)colsum)[threadIdx.x] = make_float4(0.f, 0.f, 0.f, 0.f);
    }
}

// ---------------------------------------------------------------------------
// Weight prep: W [512][128] fp32 -> W^T hi/lo bf16 [which][128 n][512 k].
// ---------------------------------------------------------------------------
__global__ void wt_kernel(const float* __restrict__ Wq, const float* __restrict__ Wk,
                          const float* __restrict__ Wv,
                          __nv_bfloat16* __restrict__ wth, __nv_bfloat16* __restrict__ wtl)
{
    __shared__ float sm[32][132];
    const int which = blockIdx.y;
    const float* W = which == 0 ? Wq : (which == 1 ? Wk : Wv);
    const int k0 = blockIdx.x * 32;
    const int t = threadIdx.x;
    #pragma unroll
    for (int l = 0; l < 8; l++) {
        int u = t + l * 128;
        int k = u >> 5, n4 = u & 31;
        float4 w = *(const float4*)&W[(size_t)(k0 + k) * 128 + n4 * 4];
        sm[k][n4*4+0] = w.x; sm[k][n4*4+1] = w.y;
        sm[k][n4*4+2] = w.z; sm[k][n4*4+3] = w.w;
    }
    __syncthreads();
    uint32_t hw[16], lw[16];
    #pragma unroll
    for (int kk = 0; kk < 32; kk += 2) {
        float a = sm[kk][t], b = sm[kk+1][t];
        __nv_bfloat16 ha = __float2bfloat16(a), hb = __float2bfloat16(b);
        hw[kk>>1] = pack_bf2(a, b);
        lw[kk>>1] = pack_bf2(a - __bfloat162float(ha), b - __bfloat162float(hb));
    }
    size_t base = ((size_t)which * 128 + t) * 512 + k0;
    #pragma unroll
    for (int s = 0; s < 4; s++) {
        *(uint4*)&wth[base + s*8] = *(uint4*)&hw[s*4];
        *(uint4*)&wtl[base + s*8] = *(uint4*)&lw[s*4];
    }
}

// ---------------------------------------------------------------------------
// QKV projection via mma.sync bf16 3-term split. M=8192, K=512, N=128.
// ---------------------------------------------------------------------------
__global__ __launch_bounds__(256, 2) void proj_mma_kernel(
    const float* __restrict__ Q, const float* __restrict__ K, const float* __restrict__ V,
    const __nv_bfloat16* __restrict__ wth, const __nv_bfloat16* __restrict__ wtl,
    const float* __restrict__ bq, const float* __restrict__ bk, const float* __restrict__ bv,
    __nv_bfloat16* __restrict__ qh, __nv_bfloat16* __restrict__ ql,
    __nv_bfloat16* __restrict__ kh, __nv_bfloat16* __restrict__ kl,
    float* __restrict__ gv)
{
    extern __shared__ char smem[];
    const int which = blockIdx.y;
    const float* X    = which == 0 ? Q  : (which == 1 ? K  : V);
    const float* bias = which == 0 ? bq : (which == 1 ? bk : bv);
    const int r0 = blockIdx.x * 128;
    const int tid = threadIdx.x, wid = tid >> 5, lid = tid & 31;
    const int wm = wid & 3, wn = wid >> 2;

    char* tXH = smem;              // 128 rows x 144B
    char* tXL = smem + 18432;
    char* tWH = smem + 36864;      // 128 n-rows x 144B
    char* tWL = smem + 55296;
    const uint32_t sXH = smem_u32(tXH), sXL = smem_u32(tXL);
    const uint32_t sWH = smem_u32(tWH), sWL = smem_u32(tWL);

    const uint32_t aOff = (uint32_t)((wm * 32 + (lid & 15)) * 144 + ((lid >> 4) << 4));
    const uint32_t bOff = (uint32_t)((wn * 64 + ((lid & 16) >> 1) + (lid & 7)) * 144
                                     + ((lid & 8) << 1));
    float acc[2][8][4] = {};

    for (int k0 = 0; k0 < 512; k0 += 64) {
        #pragma unroll
        for (int l = 0; l < 8; l++) {
            int u = tid + l * 256;
            int row = u >> 4, k4 = u & 15;
            float4 x = *(const float4*)&X[(size_t)(r0 + row) * 512 + k0 + k4 * 4];
            uint2 hi, lo; split4(x, &hi, &lo);
            *(uint2*)(tXH + row * 144 + k4 * 8) = hi;
            *(uint2*)(tXL + row * 144 + k4 * 8) = lo;
        }
        #pragma unroll
        for (int l = 0; l < 4; l++) {
            int u = tid + l * 256;
            int n = u >> 3, c = u & 7;
            size_t gidx = ((size_t)which * 128 + n) * 512 + k0 + c * 8;
            *(float4*)(tWH + n * 144 + c * 16) = *(const float4*)&wth[gidx];
            *(float4*)(tWL + n * 144 + c * 16) = *(const float4*)&wtl[gidx];
        }
        __syncthreads();

        const uint32_t qb[3] = { sXH, sXH, sXL };
        const uint32_t kb[3] = { sWH, sWL, sWH };
        #pragma unroll
        for (int t = 0; t < 3; t++) {
            const uint32_t qa = qb[t] + aOff;
            const uint32_t ka = kb[t] + bOff;
            #pragma unroll
            for (int ks = 0; ks < 4; ks++) {
                uint32_t af[2][4], bf[4][4];
                ldsm_x4(af[0], qa + ks * 32);
                ldsm_x4(af[1], qa + ks * 32 + 16 * 144);
                #pragma unroll
                for (int np = 0; np < 4; np++)
                    ldsm_x4(bf[np], ka + ks * 32 + np * 16 * 144);
                #pragma unroll
                for (int mi = 0; mi < 2; mi++)
                    #pragma unroll
                    for (int np = 0; np < 4; np++) {
                        mma_bf16(acc[mi][np*2],   af[mi], &bf[np][0]);
                        mma_bf16(acc[mi][np*2+1], af[mi], &bf[np][2]);
                    }
            }
        }
        __syncthreads();
    }

    const int g = lid >> 2, qid = lid & 3;
    #pragma unroll
    for (int mi = 0; mi < 2; mi++) {
        #pragma unroll
        for (int half = 0; half < 2; half++) {
            int r = r0 + wm * 32 + mi * 16 + half * 8 + g;
            int b = r >> 11, ii = r & 2047;
            #pragma unroll
            for (int ni = 0; ni < 8; ni++) {
                int col = wn * 64 + ni * 8 + qid * 2;
                float v0 = acc[mi][ni][half*2+0] + bias[col];
                float v1 = acc[mi][ni][half*2+1] + bias[col+1];
                int h = col >> 6, dd = col & 63;
                size_t idx = (((size_t)(b*2 + h)) * 2048 + ii) * 64 + dd;
                if (which == 2) {
                    *(float2*)&gv[idx] = make_float2(v0, v1);
                } else {
                    __nv_bfloat16 h0 = __float2bfloat16(v0), h1 = __float2bfloat16(v1);
                    uint32_t hp = pack_bf2(v0, v1);
                    uint32_t lp = pack_bf2(v0 - __bfloat162float(h0), v1 - __bfloat162float(h1));
                    __nv_bfloat16* ph = (which == 0 ? qh : kh);
                    __nv_bfloat16* pl = (which == 0 ? ql : kl);
                    *(uint32_t*)&ph[idx] = hp;
                    *(uint32_t*)&pl[idx] = lp;
                }
            }
        }
    }
}

// ---------------------------------------------------------------------------
// V transpose + split + fused colsum: v [bh][j][d] -> vt hi/lo [bh][d][j],
// colsum[bh][d] += partial. grid (16 jchunks, 8 bh), 256 thr.
// ---------------------------------------------------------------------------
__global__ void vt_kernel(const float* __restrict__ gv,
                          __nv_bfloat16* __restrict__ vth, __nv_bfloat16* __restrict__ vtl,
                          float* __restrict__ colsum)
{
    __shared__ float sm[128][68];
    __shared__ float red[256];
    const int bh = blockIdx.y;
    const int j0 = blockIdx.x * 128;
    const int tid = threadIdx.x;
    const float* v = gv + (size_t)bh * 2048 * 64;
    #pragma unroll
    for (int l = 0; l < 8; l++) {
        int u = tid + l * 256;
        int j = u >> 4, d4 = u & 15;
        float4 x = *(const float4*)&v[(size_t)(j0 + j) * 64 + d4 * 4];
        sm[j][d4*4+0] = x.x; sm[j][d4*4+1] = x.y;
        sm[j][d4*4+2] = x.z; sm[j][d4*4+3] = x.w;
    }
    __syncthreads();
    #pragma unroll
    for (int l = 0; l < 8; l++) {
        int u = tid + l * 256;
        int d = u >> 5, j4 = u & 31;
        float4 x = make_float4(sm[j4*4+0][d], sm[j4*4+1][d], sm[j4*4+2][d], sm[j4*4+3][d]);
        uint2 hi, lo; split4(x, &hi, &lo);
        size_t idx = ((size_t)bh * 64 + d) * 2048 + j0 + j4 * 4;
        *(uint2*)&vth[idx] = hi;
        *(uint2*)&vtl[idx] = lo;
    }
    // fused colsum over this j-chunk
    {
        const int d = tid & 63, part = tid >> 6;
        float s = 0.f;
        #pragma unroll 8
        for (int j = part * 32; j < part * 32 + 32; j++) s += sm[j][d];
        red[tid] = s;
        __syncthreads();
        if (tid < 64)
            atomicAdd(&colsum[bh * 64 + tid],
                      red[tid] + red[tid+64] + red[tid+128] + red[tid+192]);
    }
}

// ---------------------------------------------------------------------------
// mma.sync scores (unchanged).
// ---------------------------------------------------------------------------
__global__ __launch_bounds__(256, 2) void scores_mma_kernel(
    const __nv_bfloat16* __restrict__ gqh, const __nv_bfloat16* __restrict__ gql,
    const __nv_bfloat16* __restrict__ gkh, const __nv_bfloat16* __restrict__ gkl,
    const int* __restrict__ mask, float* __restrict__ attn, float* __restrict__ sumexp)
{
    extern __shared__ char smem[];
    const int tid = threadIdx.x, wid = tid >> 5, lid = tid & 31;
    const int bh = blockIdx.z, b = bh >> 1;
    const int i0 = blockIdx.x * 128, j0 = blockIdx.y * 128;
    const int wm = wid & 3, wn = wid >> 2;

    char* tQH = smem;
    char* tQL = smem + 18432;
    char* tKH = smem + 36864;
    char* tKL = smem + 55296;
    int*  smk = (int*)(smem + 73728);

    {
        const float4* s0 = (const float4*)(gqh + ((size_t)bh * 2048 + i0) * 64);
        const float4* s1 = (const float4*)(gql + ((size_t)bh * 2048 + i0) * 64);
        const float4* s2 = (const float4*)(gkh + ((size_t)bh * 2048 + j0) * 64);
        const float4* s3 = (const float4*)(gkl + ((size_t)bh * 2048 + j0) * 64);
        #pragma unroll
        for (int l = 0; l < 4; l++) {
            int u = tid + l * 256;
            int row = u >> 3, ch = u & 7;
            int off = row * 144 + ch * 16;
            *(float4*)(tQH + off) = s0[u];
            *(float4*)(tQL + off) = s1[u];
            *(float4*)(tKH + off) = s2[u];
            *(float4*)(tKL + off) = s3[u];
        }
    }
    if (tid < 128) smk[tid] = mask[b * 2048 + j0 + tid];
    __syncthreads();

    const uint32_t aOff = (uint32_t)((wm * 32 + (lid & 15)) * 144 + ((lid >> 4) << 4));
    const uint32_t bOff = (uint32_t)((wn * 64 + ((lid & 16) >> 1) + (lid & 7)) * 144
                                     + ((lid & 8) << 1));

    float acc[2][8][4] = {};
    const uint32_t qb[3] = { smem_u32(tQH), smem_u32(tQH), smem_u32(tQL) };
    const uint32_t kb[3] = { smem_u32(tKH), smem_u32(tKL), smem_u32(tKH) };

    #pragma unroll
    for (int t = 0; t < 3; t++) {
        const uint32_t qa = qb[t] + aOff;
        const uint32_t ka = kb[t] + bOff;
        #pragma unroll
        for (int ks = 0; ks < 4; ks++) {
            uint32_t af[2][4], bf[4][4];
            ldsm_x4(af[0], qa + ks * 32);
            ldsm_x4(af[1], qa + ks * 32 + 16 * 144);
            #pragma unroll
            for (int np = 0; np < 4; np++)
                ldsm_x4(bf[np], ka + ks * 32 + np * 16 * 144);
            #pragma unroll
            for (int mi = 0; mi < 2; mi++)
                #pragma unroll
                for (int np = 0; np < 4; np++) {
                    mma_bf16(acc[mi][np*2],   af[mi], &bf[np][0]);
                    mma_bf16(acc[mi][np*2+1], af[mi], &bf[np][2]);
                }
        }
    }
    __syncthreads();

    float* buf = (float*)smem;             // [128][132]
    const int g = lid >> 2, qid = lid & 3;
    float rs[2][2] = {};
    #pragma unroll
    for (int mi = 0; mi < 2; mi++) {
        const int row0 = wm * 32 + mi * 16 + g;
        #pragma unroll
        for (int ni = 0; ni < 8; ni++) {
            const int col = wn * 64 + ni * 8 + qid * 2;
            const int m0 = smk[col], m1 = smk[col + 1];
            float v0 = acc[mi][ni][0], v1 = acc[mi][ni][1];
            float v2 = acc[mi][ni][2], v3 = acc[mi][ni][3];
            v0 = 10.0f - 20.0f / (__expf(v0 * 0.25f) + 1.0f);
            v1 = 10.0f - 20.0f / (__expf(v1 * 0.25f) + 1.0f);
            v2 = 10.0f - 20.0f / (__expf(v2 * 0.25f) + 1.0f);
            v3 = 10.0f - 20.0f / (__expf(v3 * 0.25f) + 1.0f);
            if (m0) { v0 = -10.0f; v2 = -10.0f; }
            if (m1) { v1 = -10.0f; v3 = -10.0f; }
            rs[mi][0] += __expf(v0) + __expf(v1);
            rs[mi][1] += __expf(v2) + __expf(v3);
            *(float2*)&buf[row0 * 132 + col]       = make_float2(v0, v1);
            *(float2*)&buf[(row0 + 8) * 132 + col] = make_float2(v2, v3);
        }
    }
    #pragma unroll
    for (int mi = 0; mi < 2; mi++)
        #pragma unroll
        for (int hl = 0; hl < 2; hl++) {
            float r = rs[mi][hl];
            r += __shfl_xor_sync(0xffffffffu, r, 1);
            r += __shfl_xor_sync(0xffffffffu, r, 2);
            if (qid == 0)
                atomicAdd(&sumexp[bh * 2048 + i0 + wm * 32 + mi * 16 + hl * 8 + g], r);
        }
    __syncthreads();

    #pragma unroll
    for (int l = 0; l < 16; l++) {
        int idx = tid + l * 256;
        int row = idx >> 5, c4 = idx & 31;
        float4 v = *(const float4*)&buf[row * 132 + c4 * 4];
        *(float4*)(attn + ((size_t)bh * 2048 + i0 + row) * 2048 + j0 + c4 * 4) = v;
    }
}

// ---------------------------------------------------------------------------
__global__ void lse_kernel(float* __restrict__ sumexp)
{
    int g = blockIdx.x * 256 + threadIdx.x;
    float4 v = ((float4*)sumexp)[g];
    v.x = __logf(v.x); v.y = __logf(v.y); v.z = __logf(v.z); v.w = __logf(v.w);
    ((float4*)sumexp)[g] = v;
}

// ---------------------------------------------------------------------------
// AV via mma.sync bf16 3-term with 4-way k-split.
// ctx2[ks][bh][i][d] = sum_{j in split} x[i][j] vt[d][j]; attn -> x - lse fused.
// grid (16 itiles, 4 ksplit, 8 bh) = 512 CTAs.
// ---------------------------------------------------------------------------
__global__ __launch_bounds__(256, 2) void av_mma_kernel(
    float* __restrict__ attn,
    const __nv_bfloat16* __restrict__ vth, const __nv_bfloat16* __restrict__ vtl,
    const float* __restrict__ lse, float* __restrict__ ctx2)
{
    extern __shared__ char smem[];
    const int bh = blockIdx.z;
    const int ksplit = blockIdx.y;
    const int i0 = blockIdx.x * 128;
    const int tid = threadIdx.x, wid = tid >> 5, lid = tid & 31;
    const int wm = wid & 3, wn = wid >> 2;

    char* tAH = smem;               // 128 x 144B
    char* tAL = smem + 18432;
    char* tBH = smem + 36864;       // 64 x 144B
    char* tBL = smem + 46080;
    float* ls = (float*)(smem + 55296);   // 128
    const uint32_t sAH = smem_u32(tAH), sAL = smem_u32(tAL);
    const uint32_t sBH = smem_u32(tBH), sBL = smem_u32(tBL);

    if (tid < 128) ls[tid] = lse[bh * 2048 + i0 + tid];
    __syncthreads();

    float* a = attn + (size_t)bh * 2048 * 2048;
    const __nv_bfloat16* bh_vt = vth + (size_t)bh * 64 * 2048;
    const __nv_bfloat16* bl_vt = vtl + (size_t)bh * 64 * 2048;

    const uint32_t aOff = (uint32_t)((wm * 32 + (lid & 15)) * 144 + ((lid >> 4) << 4));
    const uint32_t bOff = (uint32_t)((wn * 32 + ((lid & 16) >> 1) + (lid & 7)) * 144
                                     + ((lid & 8) << 1));
    float acc[2][4][4] = {};

    for (int k0 = ksplit * 512; k0 < ksplit * 512 + 512; k0 += 64) {
        #pragma unroll
        for (int l = 0; l < 8; l++) {
            int u = tid + l * 256;
            int row = u >> 4, j4 = u & 15;
            size_t gi = (size_t)(i0 + row) * 2048 + k0 + j4 * 4;
            float4 x = *(const float4*)&a[gi];
            float lv = ls[row];
            *(float4*)&a[gi] = make_float4(x.x - lv, x.y - lv, x.z - lv, x.w - lv);
            uint2 hi, lo; split4(x, &hi, &lo);
            *(uint2*)(tAH + row * 144 + j4 * 8) = hi;
            *(uint2*)(tAL + row * 144 + j4 * 8) = lo;
        }
        #pragma unroll
        for (int l = 0; l < 2; l++) {
            int u = tid + l * 256;
            int d = u >> 3, c = u & 7;
            size_t gidx = (size_t)d * 2048 + k0 + c * 8;
            *(float4*)(tBH + d * 144 + c * 16) = *(const float4*)&bh_vt[gidx];
            *(float4*)(tBL + d * 144 + c * 16) = *(const float4*)&bl_vt[gidx];
        }
        __syncthreads();

        #pragma unroll
        for (int ks = 0; ks < 4; ks++) {
            uint32_t ah[2][4], al[2][4], bhf[2][4], blf[2][4];
            ldsm_x4(ah[0], sAH + aOff + ks * 32);
            ldsm_x4(ah[1], sAH + aOff + ks * 32 + 16 * 144);
            ldsm_x4(al[0], sAL + aOff + ks * 32);
            ldsm_x4(al[1], sAL + aOff + ks * 32 + 16 * 144);
            ldsm_x4(bhf[0], sBH + bOff + ks * 32);
            ldsm_x4(bhf[1], sBH + bOff + ks * 32 + 16 * 144);
            ldsm_x4(blf[0], sBL + bOff + ks * 32);
            ldsm_x4(blf[1], sBL + bOff + ks * 32 + 16 * 144);
            #pragma unroll
            for (int mi = 0; mi < 2; mi++)
                #pragma unroll
                for (int n2 = 0; n2 < 2; n2++)
                    #pragma unroll
                    for (int p = 0; p < 2; p++) {
                        float* c = acc[mi][n2*2+p];
                        mma_bf16(c, ah[mi], &bhf[n2][p*2]);
                        mma_bf16(c, ah[mi], &blf[n2][p*2]);
                        mma_bf16(c, al[mi], &bhf[n2][p*2]);
                    }
        }
        __syncthreads();
    }

    float* dst = ctx2 + ((size_t)ksplit * 8 + bh) * 2048 * 64;
    const int g = lid >> 2, qid = lid & 3;
    #pragma unroll
    for (int mi = 0; mi < 2; mi++) {
        #pragma unroll
        for (int half = 0; half < 2; half++) {
            int rl = wm * 32 + mi * 16 + half * 8 + g;
            size_t rbase = (size_t)(i0 + rl) * 64;
            #pragma unroll
            for (int ni = 0; ni < 4; ni++) {
                int col = wn * 32 + ni * 8 + qid * 2;
                *(float2*)&dst[rbase + col] =
                    make_float2(acc[mi][ni][half*2+0], acc[mi][ni][half*2+1]);
            }
        }
    }
}

// ---------------------------------------------------------------------------
// ctx = sum_s ctx2[s] - lse[i]*colsum[d]
// ---------------------------------------------------------------------------
__global__ void reduce_ctx_kernel(const float* __restrict__ ctx2,
    const float* __restrict__ lse, const float* __restrict__ colsum,
    float* __restrict__ ctx)
{
    int g = blockIdx.x * 256 + threadIdx.x;
    int elem = g * 4;
    int bh = elem >> 17;
    int i  = (elem >> 6) & 2047;
    int d  = elem & 63;
    const float4* c2 = (const float4*)ctx2;
    float4 s  = c2[g];
    float4 t1 = c2[262144 + g];
    float4 t2 = c2[524288 + g];
    float4 t3 = c2[786432 + g];
    s.x += t1.x + t2.x + t3.x; s.y += t1.y + t2.y + t3.y;
    s.z += t1.z + t2.z + t3.z; s.w += t1.w + t2.w + t3.w;
    float l = lse[bh * 2048 + i];
    float4 cs = *(const float4*)&colsum[bh * 64 + d];
    s.x -= l * cs.x; s.y -= l * cs.y; s.z -= l * cs.z; s.w -= l * cs.w;
    ((float4*)ctx)[g] = s;
}

// ---------------------------------------------------------------------------
__global__ __launch_bounds__(256) void out_kernel(
    const float* __restrict__ ctx, const float* __restrict__ Wo,
    const float* __restrict__ bo, float* __restrict__ out)
{
    __shared__ float As[16][132];
    __shared__ __align__(16) float Ws[16][128];
    const int r0 = blockIdx.x * 128, c0 = blockIdx.y * 128;
    const int tid = threadIdx.x;
    const int tx = tid & 15, ty = tid >> 4;
    float acc[8][8] = {};
    for (int k0 = 0; k0 < 128; k0 += 16) {
        #pragma unroll
        for (int l = 0; l < 2; l++) {
            int u = tid + l * 256;
            int k4 = u & 3, m = u >> 2;
            int r = r0 + m;
            int b = r >> 11, ii = r & 2047;
            int k = k0 + k4*4;
            int h = k >> 6, dd = k & 63;
            float4 xv = *(const float4*)&ctx[(((size_t)(b*2 + h)) * 2048 + ii) * 64 + dd];
            As[k4*4+0][m] = xv.x; As[k4*4+1][m] = xv.y;
            As[k4*4+2][m] = xv.z; As[k4*4+3][m] = xv.w;
        }
        #pragma unroll
        for (int l = 0; l < 2; l++) {
            int u = tid + l * 256;
            int n4 = u & 31, k = u >> 5;
            *(float4*)&Ws[k][n4*4] = *(const float4*)&Wo[(size_t)(k0 + k) * 512 + c0 + n4*4];
        }
        __syncthreads();
        #pragma unroll
        for (int k = 0; k < 16; k++) {
            float4 a0 = *(const float4*)&As[k][ty*8];
            float4 a1 = *(const float4*)&As[k][ty*8+4];
            float4 b0 = *(const float4*)&Ws[k][tx*4];
            float4 b1 = *(const float4*)&Ws[k][64 + tx*4];
            float ar[8] = {a0.x,a0.y,a0.z,a0.w,a1.x,a1.y,a1.z,a1.w};
            float br[8] = {b0.x,b0.y,b0.z,b0.w,b1.x,b1.y,b1.z,b1.w};
            #pragma unroll
            for (int i = 0; i < 8; i++)
                #pragma unroll
                for (int j = 0; j < 8; j++) acc[i][j] += ar[i] * br[j];
        }
        __syncthreads();
    }
    #pragma unroll
    for (int i = 0; i < 8; i++) {
        size_t r = (size_t)(r0 + ty*8 + i) * 512;
        #pragma unroll
        for (int half = 0; half < 2; half++) {
            int c = c0 + half*64 + tx*4;
            float4 o;
            o.x = acc[i][half*4+0] + bo[c+0];
            o.y = acc[i][half*4+1] + bo[c+1];
            o.z = acc[i][half*4+2] + bo[c+2];
            o.w = acc[i][half*4+3] + bo[c+3];
            *(float4*)&out[r + c] = o;
        }
    }
}

// ---------------------------------------------------------------------------
extern "C" void kernel_launch(void* const* d_in, const int* in_sizes, int n_in,
                              void* d_out, int out_size)
{
    const float* Q  = (const float*)d_in[0];
    const float* K  = (const float*)d_in[1];
    const float* V  = (const float*)d_in[2];
    const int*   mask = (const int*)d_in[3];   // bool -> int32 in harness
    const float* Wq = (const float*)d_in[4];
    const float* bq = (const float*)d_in[5];
    const float* Wk = (const float*)d_in[6];
    const float* bk = (const float*)d_in[7];
    const float* Wv = (const float*)d_in[8];
    const float* bv = (const float*)d_in[9];
    const float* Wo = (const float*)d_in[10];
    const float* bo = (const float*)d_in[11];

    float* out  = (float*)d_out;                      // [B, L, 512]
    float* attn = out + (size_t)4 * 2048 * 512;       // [B, H, L, L]

    float *gv, *gctx, *gctx2, *gse, *gcs;
    __nv_bfloat16 *qh, *ql, *kh, *kl, *wth, *wtl, *vth, *vtl;
    cudaGetSymbolAddress((void**)&gv,    g_v);
    cudaGetSymbolAddress((void**)&gctx,  g_ctx);
    cudaGetSymbolAddress((void**)&gctx2, g_ctx2);
    cudaGetSymbolAddress((void**)&gse,   g_sumexp);
    cudaGetSymbolAddress((void**)&gcs,   g_colsum);
    cudaGetSymbolAddress((void**)&qh,    g_qh);
    cudaGetSymbolAddress((void**)&ql,    g_ql);
    cudaGetSymbolAddress((void**)&kh,    g_kh);
    cudaGetSymbolAddress((void**)&kl,    g_kl);
    cudaGetSymbolAddress((void**)&wth,   g_wth);
    cudaGetSymbolAddress((void**)&wtl,   g_wtl);
    cudaGetSymbolAddress((void**)&vth,   g_vth);
    cudaGetSymbolAddress((void**)&vtl,   g_vtl);

    static int smem_set = 0;
    if (!smem_set) {
        cudaFuncSetAttribute(scores_mma_kernel, cudaFuncAttributeMaxDynamicSharedMemorySize, 74240);
        cudaFuncSetAttribute(proj_mma_kernel,   cudaFuncAttributeMaxDynamicSharedMemorySize, 73728);
        cudaFuncSetAttribute(av_mma_kernel,     cudaFuncAttributeMaxDynamicSharedMemorySize, 56064);
        smem_set = 1;
    }

    zero_kernel<<<17, 256>>>(gse, gcs);
    wt_kernel<<<dim3(16, 3), 128>>>(Wq, Wk, Wv, wth, wtl);
    proj_mma_kernel<<<dim3(64, 3), 256, 73728>>>(Q, K, V, wth, wtl, bq, bk, bv,
                                                 qh, ql, kh, kl, gv);
    vt_kernel<<<dim3(16, 8), 256>>>(gv, vth, vtl, gcs);
    scores_mma_kernel<<<dim3(16, 16, 8), 256, 74240>>>(qh, ql, kh, kl, mask, attn, gse);
    lse_kernel<<<16, 256>>>(gse);
    av_mma_kernel<<<dim3(16, 4, 8), 256, 56064>>>(attn, vth, vtl, gse, gctx2);
    reduce_ctx_kernel<<<1024, 256>>>(gctx2, gse, gcs, gctx);
    out_kernel<<<dim3(64, 4), 256>>>(gctx, Wo, bo, out);
}

// round 8
// speedup vs baseline: 2.0181x; 1.1202x over previous
#include <cuda_runtime.h>
#include <cuda_bf16.h>
#include <math.h>
#include <stdint.h>

#define Lseq 2048
#define BHn  8

// scratch (allocation-free rule: __device__ globals)
__device__ float g_v[BHn * Lseq * 64];
__device__ float g_ctx[BHn * Lseq * 64];
__device__ float g_ctx2[4 * BHn * Lseq * 64];   // k-split partials
__device__ float g_sumexp[BHn * Lseq];          // sumexp -> lse (in place)
__device__ float g_colsum[BHn * 64];            // per-(bh) column sums of v
__device__ __nv_bfloat16 g_qh[BHn * Lseq * 64];
__device__ __nv_bfloat16 g_ql[BHn * Lseq * 64];
__device__ __nv_bfloat16 g_kh[BHn * Lseq * 64];
__device__ __nv_bfloat16 g_kl[BHn * Lseq * 64];
__device__ __nv_bfloat16 g_wth[3 * 128 * 512];  // W^T hi  [which][n][k]
__device__ __nv_bfloat16 g_wtl[3 * 128 * 512];  // W^T lo
__device__ __nv_bfloat16 g_woth[512 * 128];     // Wo^T hi [n][k]
__device__ __nv_bfloat16 g_wotl[512 * 128];     // Wo^T lo
__device__ __nv_bfloat16 g_vth[BHn * 64 * Lseq]; // V^T hi [bh][d][j]
__device__ __nv_bfloat16 g_vtl[BHn * 64 * Lseq]; // V^T lo

__device__ __forceinline__ uint32_t smem_u32(const void* p) {
    uint32_t a;
    asm("{ .reg .u64 t; cvta.to.shared.u64 t, %1; cvt.u32.u64 %0, t; }" : "=r"(a) : "l"(p));
    return a;
}
__device__ __forceinline__ void ldsm_x4(uint32_t* r, uint32_t addr) {
    asm volatile("ldmatrix.sync.aligned.m8n8.x4.shared.b16 {%0,%1,%2,%3}, [%4];"
        : "=r"(r[0]), "=r"(r[1]), "=r"(r[2]), "=r"(r[3]) : "r"(addr));
}
__device__ __forceinline__ void mma_bf16(float* c, const uint32_t* a, const uint32_t* b) {
    asm volatile("mma.sync.aligned.m16n8k16.row.col.f32.bf16.bf16.f32 "
        "{%0,%1,%2,%3}, {%4,%5,%6,%7}, {%8,%9}, {%0,%1,%2,%3};"
        : "+f"(c[0]), "+f"(c[1]), "+f"(c[2]), "+f"(c[3])
        : "r"(a[0]), "r"(a[1]), "r"(a[2]), "r"(a[3]), "r"(b[0]), "r"(b[1]));
}
__device__ __forceinline__ uint32_t pack_bf2(float a, float b) {
    __nv_bfloat162 t;
    t.x = __float2bfloat16(a); t.y = __float2bfloat16(b);
    return *(uint32_t*)&t;
}
__device__ __forceinline__ void split4(float4 x, uint2* hi, uint2* lo) {
    __nv_bfloat16 hx = __float2bfloat16(x.x), hy = __float2bfloat16(x.y);
    __nv_bfloat16 hz = __float2bfloat16(x.z), hw = __float2bfloat16(x.w);
    __nv_bfloat162 h01; h01.x = hx; h01.y = hy;
    __nv_bfloat162 h23; h23.x = hz; h23.y = hw;
    hi->x = *(uint32_t*)&h01; hi->y = *(uint32_t*)&h23;
    __nv_bfloat162 l01, l23;
    l01.x = __float2bfloat16(x.x - __bfloat162float(hx));
    l01.y = __float2bfloat16(x.y - __bfloat162float(hy));
    l23.x = __float2bfloat16(x.z - __bfloat162float(hz));
    l23.y = __float2bfloat16(x.w - __bfloat162float(hw));
    lo->x = *(uint32_t*)&l01; lo->y = *(uint32_t*)&l23;
}

// ---------------------------------------------------------------------------
__global__ void zero_kernel(float* __restrict__ sumexp, float* __restrict__ colsum)
{
    if (blockIdx.x < 16) {
        int g = blockIdx.x * 256 + threadIdx.x;
        ((float4*)sumexp)[g] = make_float4(0.f, 0.f, 0.f, 0.f);
    } else if (threadIdx.x < 128) {
        ((float4*)colsum)[threadIdx.x] = make_float4(0.f, 0.f, 0.f, 0.f);
    }
}

// ---------------------------------------------------------------------------
// Weight prep: W [512][128] fp32 -> W^T hi/lo bf16 [which][128 n][512 k].
// ---------------------------------------------------------------------------
__global__ void wt_kernel(const float* __restrict__ Wq, const float* __restrict__ Wk,
                          const float* __restrict__ Wv,
                          __nv_bfloat16* __restrict__ wth, __nv_bfloat16* __restrict__ wtl)
{
    __shared__ float sm[32][132];
    const int which = blockIdx.y;
    const float* W = which == 0 ? Wq : (which == 1 ? Wk : Wv);
    const int k0 = blockIdx.x * 32;
    const int t = threadIdx.x;
    #pragma unroll
    for (int l = 0; l < 8; l++) {
        int u = t + l * 128;
        int k = u >> 5, n4 = u & 31;
        float4 w = *(const float4*)&W[(size_t)(k0 + k) * 128 + n4 * 4];
        sm[k][n4*4+0] = w.x; sm[k][n4*4+1] = w.y;
        sm[k][n4*4+2] = w.z; sm[k][n4*4+3] = w.w;
    }
    __syncthreads();
    uint32_t hw[16], lw[16];
    #pragma unroll
    for (int kk = 0; kk < 32; kk += 2) {
        float a = sm[kk][t], b = sm[kk+1][t];
        __nv_bfloat16 ha = __float2bfloat16(a), hb = __float2bfloat16(b);
        hw[kk>>1] = pack_bf2(a, b);
        lw[kk>>1] = pack_bf2(a - __bfloat162float(ha), b - __bfloat162float(hb));
    }
    size_t base = ((size_t)which * 128 + t) * 512 + k0;
    #pragma unroll
    for (int s = 0; s < 4; s++) {
        *(uint4*)&wth[base + s*8] = *(uint4*)&hw[s*4];
        *(uint4*)&wtl[base + s*8] = *(uint4*)&lw[s*4];
    }
}

// ---------------------------------------------------------------------------
// Wo prep: Wo [128 k][512 n] fp32 -> Wo^T hi/lo bf16 [512 n][128 k].
// grid 16 CTAs (32 n each), 256 thr.
// ---------------------------------------------------------------------------
__global__ void wo_kernel(const float* __restrict__ Wo,
                          __nv_bfloat16* __restrict__ woth, __nv_bfloat16* __restrict__ wotl)
{
    __shared__ float sm[128][33];
    const int n0 = blockIdx.x * 32;
    const int tid = threadIdx.x;
    #pragma unroll
    for (int l = 0; l < 16; l++) {
        int u = tid + l * 256;
        int k = u >> 5, n = u & 31;
        sm[k][n] = Wo[(size_t)k * 512 + n0 + n];
    }
    __syncthreads();
    #pragma unroll
    for (int l = 0; l < 16; l++) {
        int u = tid + l * 256;
        int n = u >> 7, k = u & 127;
        float v = sm[k][n];
        __nv_bfloat16 h = __float2bfloat16(v);
        woth[(size_t)(n0 + n) * 128 + k] = h;
        wotl[(size_t)(n0 + n) * 128 + k] = __float2bfloat16(v - __bfloat162float(h));
    }
}

// ---------------------------------------------------------------------------
// QKV projection via mma.sync bf16 3-term split. M=8192, K=512, N=128.
// Fragments loaded ONCE per k-step; 3 terms issued from registers.
// ---------------------------------------------------------------------------
__global__ __launch_bounds__(256, 2) void proj_mma_kernel(
    const float* __restrict__ Q, const float* __restrict__ K, const float* __restrict__ V,
    const __nv_bfloat16* __restrict__ wth, const __nv_bfloat16* __restrict__ wtl,
    const float* __restrict__ bq, const float* __restrict__ bk, const float* __restrict__ bv,
    __nv_bfloat16* __restrict__ qh, __nv_bfloat16* __restrict__ ql,
    __nv_bfloat16* __restrict__ kh, __nv_bfloat16* __restrict__ kl,
    float* __restrict__ gv)
{
    extern __shared__ char smem[];
    const int which = blockIdx.y;
    const float* X    = which == 0 ? Q  : (which == 1 ? K  : V);
    const float* bias = which == 0 ? bq : (which == 1 ? bk : bv);
    const int r0 = blockIdx.x * 128;
    const int tid = threadIdx.x, wid = tid >> 5, lid = tid & 31;
    const int wm = wid & 3, wn = wid >> 2;

    char* tXH = smem;              // 128 rows x 144B
    char* tXL = smem + 18432;
    char* tWH = smem + 36864;      // 128 n-rows x 144B
    char* tWL = smem + 55296;
    const uint32_t sXH = smem_u32(tXH), sXL = smem_u32(tXL);
    const uint32_t sWH = smem_u32(tWH), sWL = smem_u32(tWL);

    const uint32_t aOff = (uint32_t)((wm * 32 + (lid & 15)) * 144 + ((lid >> 4) << 4));
    const uint32_t bOff = (uint32_t)((wn * 64 + ((lid & 16) >> 1) + (lid & 7)) * 144
                                     + ((lid & 8) << 1));
    float acc[2][8][4] = {};

    for (int k0 = 0; k0 < 512; k0 += 64) {
        #pragma unroll
        for (int l = 0; l < 8; l++) {
            int u = tid + l * 256;
            int row = u >> 4, k4 = u & 15;
            float4 x = *(const float4*)&X[(size_t)(r0 + row) * 512 + k0 + k4 * 4];
            uint2 hi, lo; split4(x, &hi, &lo);
            *(uint2*)(tXH + row * 144 + k4 * 8) = hi;
            *(uint2*)(tXL + row * 144 + k4 * 8) = lo;
        }
        #pragma unroll
        for (int l = 0; l < 4; l++) {
            int u = tid + l * 256;
            int n = u >> 3, c = u & 7;
            size_t gidx = ((size_t)which * 128 + n) * 512 + k0 + c * 8;
            *(float4*)(tWH + n * 144 + c * 16) = *(const float4*)&wth[gidx];
            *(float4*)(tWL + n * 144 + c * 16) = *(const float4*)&wtl[gidx];
        }
        __syncthreads();

        #pragma unroll
        for (int ks = 0; ks < 4; ks++) {
            uint32_t ah[2][4], al[2][4], bh[4][4], bl[4][4];
            ldsm_x4(ah[0], sXH + aOff + ks * 32);
            ldsm_x4(ah[1], sXH + aOff + ks * 32 + 16 * 144);
            ldsm_x4(al[0], sXL + aOff + ks * 32);
            ldsm_x4(al[1], sXL + aOff + ks * 32 + 16 * 144);
            #pragma unroll
            for (int np = 0; np < 4; np++) {
                ldsm_x4(bh[np], sWH + bOff + ks * 32 + np * 16 * 144);
                ldsm_x4(bl[np], sWL + bOff + ks * 32 + np * 16 * 144);
            }
            #pragma unroll
            for (int mi = 0; mi < 2; mi++)
                #pragma unroll
                for (int np = 0; np < 4; np++) {
                    mma_bf16(acc[mi][np*2],   ah[mi], &bh[np][0]);
                    mma_bf16(acc[mi][np*2+1], ah[mi], &bh[np][2]);
                    mma_bf16(acc[mi][np*2],   ah[mi], &bl[np][0]);
                    mma_bf16(acc[mi][np*2+1], ah[mi], &bl[np][2]);
                    mma_bf16(acc[mi][np*2],   al[mi], &bh[np][0]);
                    mma_bf16(acc[mi][np*2+1], al[mi], &bh[np][2]);
                }
        }
        __syncthreads();
    }

    const int g = lid >> 2, qid = lid & 3;
    #pragma unroll
    for (int mi = 0; mi < 2; mi++) {
        #pragma unroll
        for (int half = 0; half < 2; half++) {
            int r = r0 + wm * 32 + mi * 16 + half * 8 + g;
            int b = r >> 11, ii = r & 2047;
            #pragma unroll
            for (int ni = 0; ni < 8; ni++) {
                int col = wn * 64 + ni * 8 + qid * 2;
                float v0 = acc[mi][ni][half*2+0] + bias[col];
                float v1 = acc[mi][ni][half*2+1] + bias[col+1];
                int h = col >> 6, dd = col & 63;
                size_t idx = (((size_t)(b*2 + h)) * 2048 + ii) * 64 + dd;
                if (which == 2) {
                    *(float2*)&gv[idx] = make_float2(v0, v1);
                } else {
                    __nv_bfloat16 h0 = __float2bfloat16(v0), h1 = __float2bfloat16(v1);
                    uint32_t hp = pack_bf2(v0, v1);
                    uint32_t lp = pack_bf2(v0 - __bfloat162float(h0), v1 - __bfloat162float(h1));
                    __nv_bfloat16* ph = (which == 0 ? qh : kh);
                    __nv_bfloat16* pl = (which == 0 ? ql : kl);
                    *(uint32_t*)&ph[idx] = hp;
                    *(uint32_t*)&pl[idx] = lp;
                }
            }
        }
    }
}

// ---------------------------------------------------------------------------
// V transpose + split + fused colsum.
// ---------------------------------------------------------------------------
__global__ void vt_kernel(const float* __restrict__ gv,
                          __nv_bfloat16* __restrict__ vth, __nv_bfloat16* __restrict__ vtl,
                          float* __restrict__ colsum)
{
    __shared__ float sm[128][68];
    __shared__ float red[256];
    const int bh = blockIdx.y;
    const int j0 = blockIdx.x * 128;
    const int tid = threadIdx.x;
    const float* v = gv + (size_t)bh * 2048 * 64;
    #pragma unroll
    for (int l = 0; l < 8; l++) {
        int u = tid + l * 256;
        int j = u >> 4, d4 = u & 15;
        float4 x = *(const float4*)&v[(size_t)(j0 + j) * 64 + d4 * 4];
        sm[j][d4*4+0] = x.x; sm[j][d4*4+1] = x.y;
        sm[j][d4*4+2] = x.z; sm[j][d4*4+3] = x.w;
    }
    __syncthreads();
    #pragma unroll
    for (int l = 0; l < 8; l++) {
        int u = tid + l * 256;
        int d = u >> 5, j4 = u & 31;
        float4 x = make_float4(sm[j4*4+0][d], sm[j4*4+1][d], sm[j4*4+2][d], sm[j4*4+3][d]);
        uint2 hi, lo; split4(x, &hi, &lo);
        size_t idx = ((size_t)bh * 64 + d) * 2048 + j0 + j4 * 4;
        *(uint2*)&vth[idx] = hi;
        *(uint2*)&vtl[idx] = lo;
    }
    {
        const int d = tid & 63, part = tid >> 6;
        float s = 0.f;
        #pragma unroll 8
        for (int j = part * 32; j < part * 32 + 32; j++) s += sm[j][d];
        red[tid] = s;
        __syncthreads();
        if (tid < 64)
            atomicAdd(&colsum[bh * 64 + tid],
                      red[tid] + red[tid+64] + red[tid+128] + red[tid+192]);
    }
}

// ---------------------------------------------------------------------------
// mma.sync scores; fragments loaded once per k-step, 3 terms from registers.
// ---------------------------------------------------------------------------
__global__ __launch_bounds__(256, 2) void scores_mma_kernel(
    const __nv_bfloat16* __restrict__ gqh, const __nv_bfloat16* __restrict__ gql,
    const __nv_bfloat16* __restrict__ gkh, const __nv_bfloat16* __restrict__ gkl,
    const int* __restrict__ mask, float* __restrict__ attn, float* __restrict__ sumexp)
{
    extern __shared__ char smem[];
    const int tid = threadIdx.x, wid = tid >> 5, lid = tid & 31;
    const int bh = blockIdx.z, b = bh >> 1;
    const int i0 = blockIdx.x * 128, j0 = blockIdx.y * 128;
    const int wm = wid & 3, wn = wid >> 2;

    char* tQH = smem;
    char* tQL = smem + 18432;
    char* tKH = smem + 36864;
    char* tKL = smem + 55296;
    int*  smk = (int*)(smem + 73728);

    {
        const float4* s0 = (const float4*)(gqh + ((size_t)bh * 2048 + i0) * 64);
        const float4* s1 = (const float4*)(gql + ((size_t)bh * 2048 + i0) * 64);
        const float4* s2 = (const float4*)(gkh + ((size_t)bh * 2048 + j0) * 64);
        const float4* s3 = (const float4*)(gkl + ((size_t)bh * 2048 + j0) * 64);
        #pragma unroll
        for (int l = 0; l < 4; l++) {
            int u = tid + l * 256;
            int row = u >> 3, ch = u & 7;
            int off = row * 144 + ch * 16;
            *(float4*)(tQH + off) = s0[u];
            *(float4*)(tQL + off) = s1[u];
            *(float4*)(tKH + off) = s2[u];
            *(float4*)(tKL + off) = s3[u];
        }
    }
    if (tid < 128) smk[tid] = mask[b * 2048 + j0 + tid];
    __syncthreads();

    const uint32_t aOff = (uint32_t)((wm * 32 + (lid & 15)) * 144 + ((lid >> 4) << 4));
    const uint32_t bOff = (uint32_t)((wn * 64 + ((lid & 16) >> 1) + (lid & 7)) * 144
                                     + ((lid & 8) << 1));
    const uint32_t sQH = smem_u32(tQH), sQL = smem_u32(tQL);
    const uint32_t sKH = smem_u32(tKH), sKL = smem_u32(tKL);

    float acc[2][8][4] = {};
    #pragma unroll
    for (int ks = 0; ks < 4; ks++) {
        uint32_t ah[2][4], al[2][4], bhf[4][4], blf[4][4];
        ldsm_x4(ah[0], sQH + aOff + ks * 32);
        ldsm_x4(ah[1], sQH + aOff + ks * 32 + 16 * 144);
        ldsm_x4(al[0], sQL + aOff + ks * 32);
        ldsm_x4(al[1], sQL + aOff + ks * 32 + 16 * 144);
        #pragma unroll
        for (int np = 0; np < 4; np++) {
            ldsm_x4(bhf[np], sKH + bOff + ks * 32 + np * 16 * 144);
            ldsm_x4(blf[np], sKL + bOff + ks * 32 + np * 16 * 144);
        }
        #pragma unroll
        for (int mi = 0; mi < 2; mi++)
            #pragma unroll
            for (int np = 0; np < 4; np++) {
                mma_bf16(acc[mi][np*2],   ah[mi], &bhf[np][0]);
                mma_bf16(acc[mi][np*2+1], ah[mi], &bhf[np][2]);
                mma_bf16(acc[mi][np*2],   ah[mi], &blf[np][0]);
                mma_bf16(acc[mi][np*2+1], ah[mi], &blf[np][2]);
                mma_bf16(acc[mi][np*2],   al[mi], &bhf[np][0]);
                mma_bf16(acc[mi][np*2+1], al[mi], &bhf[np][2]);
            }
    }
    __syncthreads();

    float* buf = (float*)smem;             // [128][132]
    const int g = lid >> 2, qid = lid & 3;
    float rs[2][2] = {};
    #pragma unroll
    for (int mi = 0; mi < 2; mi++) {
        const int row0 = wm * 32 + mi * 16 + g;
        #pragma unroll
        for (int ni = 0; ni < 8; ni++) {
            const int col = wn * 64 + ni * 8 + qid * 2;
            const int m0 = smk[col], m1 = smk[col + 1];
            float v0 = acc[mi][ni][0], v1 = acc[mi][ni][1];
            float v2 = acc[mi][ni][2], v3 = acc[mi][ni][3];
            v0 = 10.0f - 20.0f / (__expf(v0 * 0.25f) + 1.0f);
            v1 = 10.0f - 20.0f / (__expf(v1 * 0.25f) + 1.0f);
            v2 = 10.0f - 20.0f / (__expf(v2 * 0.25f) + 1.0f);
            v3 = 10.0f - 20.0f / (__expf(v3 * 0.25f) + 1.0f);
            if (m0) { v0 = -10.0f; v2 = -10.0f; }
            if (m1) { v1 = -10.0f; v3 = -10.0f; }
            rs[mi][0] += __expf(v0) + __expf(v1);
            rs[mi][1] += __expf(v2) + __expf(v3);
            *(float2*)&buf[row0 * 132 + col]       = make_float2(v0, v1);
            *(float2*)&buf[(row0 + 8) * 132 + col] = make_float2(v2, v3);
        }
    }
    #pragma unroll
    for (int mi = 0; mi < 2; mi++)
        #pragma unroll
        for (int hl = 0; hl < 2; hl++) {
            float r = rs[mi][hl];
            r += __shfl_xor_sync(0xffffffffu, r, 1);
            r += __shfl_xor_sync(0xffffffffu, r, 2);
            if (qid == 0)
                atomicAdd(&sumexp[bh * 2048 + i0 + wm * 32 + mi * 16 + hl * 8 + g], r);
        }
    __syncthreads();

    #pragma unroll
    for (int l = 0; l < 16; l++) {
        int idx = tid + l * 256;
        int row = idx >> 5, c4 = idx & 31;
        float4 v = *(const float4*)&buf[row * 132 + c4 * 4];
        *(float4*)(attn + ((size_t)bh * 2048 + i0 + row) * 2048 + j0 + c4 * 4) = v;
    }
}

// ---------------------------------------------------------------------------
__global__ void lse_kernel(float* __restrict__ sumexp)
{
    int g = blockIdx.x * 256 + threadIdx.x;
    float4 v = ((float4*)sumexp)[g];
    v.x = __logf(v.x); v.y = __logf(v.y); v.z = __logf(v.z); v.w = __logf(v.w);
    ((float4*)sumexp)[g] = v;
}

// ---------------------------------------------------------------------------
// AV via mma.sync bf16 3-term, 4-way k-split (unchanged).
// ---------------------------------------------------------------------------
__global__ __launch_bounds__(256, 2) void av_mma_kernel(
    float* __restrict__ attn,
    const __nv_bfloat16* __restrict__ vth, const __nv_bfloat16* __restrict__ vtl,
    const float* __restrict__ lse, float* __restrict__ ctx2)
{
    extern __shared__ char smem[];
    const int bh = blockIdx.z;
    const int ksplit = blockIdx.y;
    const int i0 = blockIdx.x * 128;
    const int tid = threadIdx.x, wid = tid >> 5, lid = tid & 31;
    const int wm = wid & 3, wn = wid >> 2;

    char* tAH = smem;               // 128 x 144B
    char* tAL = smem + 18432;
    char* tBH = smem + 36864;       // 64 x 144B
    char* tBL = smem + 46080;
    float* ls = (float*)(smem + 55296);   // 128
    const uint32_t sAH = smem_u32(tAH), sAL = smem_u32(tAL);
    const uint32_t sBH = smem_u32(tBH), sBL = smem_u32(tBL);

    if (tid < 128) ls[tid] = lse[bh * 2048 + i0 + tid];
    __syncthreads();

    float* a = attn + (size_t)bh * 2048 * 2048;
    const __nv_bfloat16* bh_vt = vth + (size_t)bh * 64 * 2048;
    const __nv_bfloat16* bl_vt = vtl + (size_t)bh * 64 * 2048;

    const uint32_t aOff = (uint32_t)((wm * 32 + (lid & 15)) * 144 + ((lid >> 4) << 4));
    const uint32_t bOff = (uint32_t)((wn * 32 + ((lid & 16) >> 1) + (lid & 7)) * 144
                                     + ((lid & 8) << 1));
    float acc[2][4][4] = {};

    for (int k0 = ksplit * 512; k0 < ksplit * 512 + 512; k0 += 64) {
        #pragma unroll
        for (int l = 0; l < 8; l++) {
            int u = tid + l * 256;
            int row = u >> 4, j4 = u & 15;
            size_t gi = (size_t)(i0 + row) * 2048 + k0 + j4 * 4;
            float4 x = *(const float4*)&a[gi];
            float lv = ls[row];
            *(float4*)&a[gi] = make_float4(x.x - lv, x.y - lv, x.z - lv, x.w - lv);
            uint2 hi, lo; split4(x, &hi, &lo);
            *(uint2*)(tAH + row * 144 + j4 * 8) = hi;
            *(uint2*)(tAL + row * 144 + j4 * 8) = lo;
        }
        #pragma unroll
        for (int l = 0; l < 2; l++) {
            int u = tid + l * 256;
            int d = u >> 3, c = u & 7;
            size_t gidx = (size_t)d * 2048 + k0 + c * 8;
            *(float4*)(tBH + d * 144 + c * 16) = *(const float4*)&bh_vt[gidx];
            *(float4*)(tBL + d * 144 + c * 16) = *(const float4*)&bl_vt[gidx];
        }
        __syncthreads();

        #pragma unroll
        for (int ks = 0; ks < 4; ks++) {
            uint32_t ah[2][4], al[2][4], bhf[2][4], blf[2][4];
            ldsm_x4(ah[0], sAH + aOff + ks * 32);
            ldsm_x4(ah[1], sAH + aOff + ks * 32 + 16 * 144);
            ldsm_x4(al[0], sAL + aOff + ks * 32);
            ldsm_x4(al[1], sAL + aOff + ks * 32 + 16 * 144);
            ldsm_x4(bhf[0], sBH + bOff + ks * 32);
            ldsm_x4(bhf[1], sBH + bOff + ks * 32 + 16 * 144);
            ldsm_x4(blf[0], sBL + bOff + ks * 32);
            ldsm_x4(blf[1], sBL + bOff + ks * 32 + 16 * 144);
            #pragma unroll
            for (int mi = 0; mi < 2; mi++)
                #pragma unroll
                for (int n2 = 0; n2 < 2; n2++)
                    #pragma unroll
                    for (int p = 0; p < 2; p++) {
                        float* c = acc[mi][n2*2+p];
                        mma_bf16(c, ah[mi], &bhf[n2][p*2]);
                        mma_bf16(c, ah[mi], &blf[n2][p*2]);
                        mma_bf16(c, al[mi], &bhf[n2][p*2]);
                    }
        }
        __syncthreads();
    }

    float* dst = ctx2 + ((size_t)ksplit * 8 + bh) * 2048 * 64;
    const int g = lid >> 2, qid = lid & 3;
    #pragma unroll
    for (int mi = 0; mi < 2; mi++) {
        #pragma unroll
        for (int half = 0; half < 2; half++) {
            int rl = wm * 32 + mi * 16 + half * 8 + g;
            size_t rbase = (size_t)(i0 + rl) * 64;
            #pragma unroll
            for (int ni = 0; ni < 4; ni++) {
                int col = wn * 32 + ni * 8 + qid * 2;
                *(float2*)&dst[rbase + col] =
                    make_float2(acc[mi][ni][half*2+0], acc[mi][ni][half*2+1]);
            }
        }
    }
}

// ---------------------------------------------------------------------------
__global__ void reduce_ctx_kernel(const float* __restrict__ ctx2,
    const float* __restrict__ lse, const float* __restrict__ colsum,
    float* __restrict__ ctx)
{
    int g = blockIdx.x * 256 + threadIdx.x;
    int elem = g * 4;
    int bh = elem >> 17;
    int i  = (elem >> 6) & 2047;
    int d  = elem & 63;
    const float4* c2 = (const float4*)ctx2;
    float4 s  = c2[g];
    float4 t1 = c2[262144 + g];
    float4 t2 = c2[524288 + g];
    float4 t3 = c2[786432 + g];
    s.x += t1.x + t2.x + t3.x; s.y += t1.y + t2.y + t3.y;
    s.z += t1.z + t2.z + t3.z; s.w += t1.w + t2.w + t3.w;
    float l = lse[bh * 2048 + i];
    float4 cs = *(const float4*)&colsum[bh * 64 + d];
    s.x -= l * cs.x; s.y -= l * cs.y; s.z -= l * cs.z; s.w -= l * cs.w;
    ((float4*)ctx)[g] = s;
}

// ---------------------------------------------------------------------------
// Output proj via mma.sync bf16 3-term. M=8192, K=128 (2 chunks), N=512.
// grid (64 rows, 4 ncols), ctx split on load, Wo pre-split.
// ---------------------------------------------------------------------------
__global__ __launch_bounds__(256, 2) void out_mma_kernel(
    const float* __restrict__ ctx,
    const __nv_bfloat16* __restrict__ woth, const __nv_bfloat16* __restrict__ wotl,
    const float* __restrict__ bo, float* __restrict__ out)
{
    extern __shared__ char smem[];
    const int r0 = blockIdx.x * 128, c0 = blockIdx.y * 128;
    const int tid = threadIdx.x, wid = tid >> 5, lid = tid & 31;
    const int wm = wid & 3, wn = wid >> 2;

    char* tAH = smem;              // 128 rows x 144B
    char* tAL = smem + 18432;
    char* tBH = smem + 36864;      // 128 n x 144B
    char* tBL = smem + 55296;
    const uint32_t sAH = smem_u32(tAH), sAL = smem_u32(tAL);
    const uint32_t sBH = smem_u32(tBH), sBL = smem_u32(tBL);

    const uint32_t aOff = (uint32_t)((wm * 32 + (lid & 15)) * 144 + ((lid >> 4) << 4));
    const uint32_t bOff = (uint32_t)((wn * 64 + ((lid & 16) >> 1) + (lid & 7)) * 144
                                     + ((lid & 8) << 1));
    float acc[2][8][4] = {};

    for (int h = 0; h < 2; h++) {      // k chunk = head
        #pragma unroll
        for (int l = 0; l < 8; l++) {
            int u = tid + l * 256;
            int row = u >> 4, k4 = u & 15;
            int r = r0 + row;
            int b = r >> 11, ii = r & 2047;
            float4 x = *(const float4*)&ctx[(((size_t)(b*2 + h)) * 2048 + ii) * 64 + k4 * 4];
            uint2 hi, lo; split4(x, &hi, &lo);
            *(uint2*)(tAH + row * 144 + k4 * 8) = hi;
            *(uint2*)(tAL + row * 144 + k4 * 8) = lo;
        }
        #pragma unroll
        for (int l = 0; l < 4; l++) {
            int u = tid + l * 256;
            int n = u >> 3, c = u & 7;
            size_t gidx = (size_t)(c0 + n) * 128 + h * 64 + c * 8;
            *(float4*)(tBH + n * 144 + c * 16) = *(const float4*)&woth[gidx];
            *(float4*)(tBL + n * 144 + c * 16) = *(const float4*)&wotl[gidx];
        }
        __syncthreads();

        #pragma unroll
        for (int ks = 0; ks < 4; ks++) {
            uint32_t ah[2][4], al[2][4], bh[4][4], bl[4][4];
            ldsm_x4(ah[0], sAH + aOff + ks * 32);
            ldsm_x4(ah[1], sAH + aOff + ks * 32 + 16 * 144);
            ldsm_x4(al[0], sAL + aOff + ks * 32);
            ldsm_x4(al[1], sAL + aOff + ks * 32 + 16 * 144);
            #pragma unroll
            for (int np = 0; np < 4; np++) {
                ldsm_x4(bh[np], sBH + bOff + ks * 32 + np * 16 * 144);
                ldsm_x4(bl[np], sBL + bOff + ks * 32 + np * 16 * 144);
            }
            #pragma unroll
            for (int mi = 0; mi < 2; mi++)
                #pragma unroll
                for (int np = 0; np < 4; np++) {
                    mma_bf16(acc[mi][np*2],   ah[mi], &bh[np][0]);
                    mma_bf16(acc[mi][np*2+1], ah[mi], &bh[np][2]);
                    mma_bf16(acc[mi][np*2],   ah[mi], &bl[np][0]);
                    mma_bf16(acc[mi][np*2+1], ah[mi], &bl[np][2]);
                    mma_bf16(acc[mi][np*2],   al[mi], &bh[np][0]);
                    mma_bf16(acc[mi][np*2+1], al[mi], &bh[np][2]);
                }
        }
        __syncthreads();
    }

    const int g = lid >> 2, qid = lid & 3;
    #pragma unroll
    for (int mi = 0; mi < 2; mi++) {
        #pragma unroll
        for (int half = 0; half < 2; half++) {
            int r = r0 + wm * 32 + mi * 16 + half * 8 + g;
            #pragma unroll
            for (int ni = 0; ni < 8; ni++) {
                int col = c0 + wn * 64 + ni * 8 + qid * 2;
                float v0 = acc[mi][ni][half*2+0] + bo[col];
                float v1 = acc[mi][ni][half*2+1] + bo[col+1];
                *(float2*)&out[(size_t)r * 512 + col] = make_float2(v0, v1);
            }
        }
    }
}

// ---------------------------------------------------------------------------
extern "C" void kernel_launch(void* const* d_in, const int* in_sizes, int n_in,
                              void* d_out, int out_size)
{
    const float* Q  = (const float*)d_in[0];
    const float* K  = (const float*)d_in[1];
    const float* V  = (const float*)d_in[2];
    const int*   mask = (const int*)d_in[3];   // bool -> int32 in harness
    const float* Wq = (const float*)d_in[4];
    const float* bq = (const float*)d_in[5];
    const float* Wk = (const float*)d_in[6];
    const float* bk = (const float*)d_in[7];
    const float* Wv = (const float*)d_in[8];
    const float* bv = (const float*)d_in[9];
    const float* Wo = (const float*)d_in[10];
    const float* bo = (const float*)d_in[11];

    float* out  = (float*)d_out;                      // [B, L, 512]
    float* attn = out + (size_t)4 * 2048 * 512;       // [B, H, L, L]

    float *gv, *gctx, *gctx2, *gse, *gcs;
    __nv_bfloat16 *qh, *ql, *kh, *kl, *wth, *wtl, *woth, *wotl, *vth, *vtl;
    cudaGetSymbolAddress((void**)&gv,    g_v);
    cudaGetSymbolAddress((void**)&gctx,  g_ctx);
    cudaGetSymbolAddress((void**)&gctx2, g_ctx2);
    cudaGetSymbolAddress((void**)&gse,   g_sumexp);
    cudaGetSymbolAddress((void**)&gcs,   g_colsum);
    cudaGetSymbolAddress((void**)&qh,    g_qh);
    cudaGetSymbolAddress((void**)&ql,    g_ql);
    cudaGetSymbolAddress((void**)&kh,    g_kh);
    cudaGetSymbolAddress((void**)&kl,    g_kl);
    cudaGetSymbolAddress((void**)&wth,   g_wth);
    cudaGetSymbolAddress((void**)&wtl,   g_wtl);
    cudaGetSymbolAddress((void**)&woth,  g_woth);
    cudaGetSymbolAddress((void**)&wotl,  g_wotl);
    cudaGetSymbolAddress((void**)&vth,   g_vth);
    cudaGetSymbolAddress((void**)&vtl,   g_vtl);

    static int smem_set = 0;
    if (!smem_set) {
        cudaFuncSetAttribute(scores_mma_kernel, cudaFuncAttributeMaxDynamicSharedMemorySize, 74240);
        cudaFuncSetAttribute(proj_mma_kernel,   cudaFuncAttributeMaxDynamicSharedMemorySize, 73728);
        cudaFuncSetAttribute(av_mma_kernel,     cudaFuncAttributeMaxDynamicSharedMemorySize, 56064);
        cudaFuncSetAttribute(out_mma_kernel,    cudaFuncAttributeMaxDynamicSharedMemorySize, 73728);
        smem_set = 1;
    }

    zero_kernel<<<17, 256>>>(gse, gcs);
    wt_kernel<<<dim3(16, 3), 128>>>(Wq, Wk, Wv, wth, wtl);
    wo_kernel<<<16, 256>>>(Wo, woth, wotl);
    proj_mma_kernel<<<dim3(64, 3), 256, 73728>>>(Q, K, V, wth, wtl, bq, bk, bv,
                                                 qh, ql, kh, kl, gv);
    vt_kernel<<<dim3(16, 8), 256>>>(gv, vth, vtl, gcs);
    scores_mma_kernel<<<dim3(16, 16, 8), 256, 74240>>>(qh, ql, kh, kl, mask, attn, gse);
    lse_kernel<<<16, 256>>>(gse);
    av_mma_kernel<<<dim3(16, 4, 8), 256, 56064>>>(attn, vth, vtl, gse, gctx2);
    reduce_ctx_kernel<<<1024, 256>>>(gctx2, gse, gcs, gctx);
    out_mma_kernel<<<dim3(64, 4), 256, 73728>>>(gctx, woth, wotl, bo, out);
}